// round 10
// baseline (speedup 1.0000x reference)
#include <cuda_runtime.h>
#include <cuda_bf16.h>
#include <cstdint>

#define B_  4
#define S_  1024
#define D_  1024
#define H_  16
#define HD_ 64
#define M_  (B_ * S_)        // 4096 rows
#define TD_ (3 * D_)         // 3072
#define NH_ (B_ * H_)        // 64 head-batches
#define NEG_ 10000.0f

// ---------------------------------------------------------------------------
// Scratch (allocation-free rule: __device__ globals)
// ---------------------------------------------------------------------------
__device__ __nv_bfloat16 g_qh[(size_t)NH_ * S_ * HD_];  // [head, s, 64]
__device__ __nv_bfloat16 g_ql[(size_t)NH_ * S_ * HD_];
__device__ __nv_bfloat16 g_kh[(size_t)NH_ * S_ * HD_];
__device__ __nv_bfloat16 g_kl[(size_t)NH_ * S_ * HD_];
__device__ __nv_bfloat16 g_vh[(size_t)NH_ * S_ * HD_];
__device__ __nv_bfloat16 g_vl[(size_t)NH_ * S_ * HD_];
__device__ __nv_bfloat16 g_ph[(size_t)NH_ * S_ * S_];   // probs hi/lo
__device__ __nv_bfloat16 g_pl[(size_t)NH_ * S_ * S_];
__device__ __nv_bfloat16 g_ch[(size_t)M_ * D_];          // ctx hi/lo row-major
__device__ __nv_bfloat16 g_cl[(size_t)M_ * D_];

__device__ __nv_bfloat16 g_xh[(size_t)M_ * D_];          // x hi/lo row-major
__device__ __nv_bfloat16 g_xl[(size_t)M_ * D_];
__device__ __nv_bfloat16 g_wah[(size_t)TD_ * D_];        // w_attn^T hi/lo
__device__ __nv_bfloat16 g_wal[(size_t)TD_ * D_];
__device__ __nv_bfloat16 g_wph[(size_t)D_ * D_];         // w_proj^T hi/lo
__device__ __nv_bfloat16 g_wpl[(size_t)D_ * D_];

__device__ __forceinline__ uint32_t smem_u32(const void* p) {
    uint32_t a;
    asm("{ .reg .u64 t; cvta.to.shared.u64 t, %1; cvt.u32.u64 %0, t; }" : "=r"(a) : "l"(p));
    return a;
}
__device__ __forceinline__ void cp16(uint32_t s, const void* g) {
    asm volatile("cp.async.ca.shared.global [%0], [%1], 16;" :: "r"(s), "l"(g));
}
__device__ __forceinline__ void ldm_x4(uint32_t* f, uint32_t addr) {
    asm volatile("ldmatrix.sync.aligned.m8n8.x4.shared.b16 {%0,%1,%2,%3}, [%4];"
                 : "=r"(f[0]), "=r"(f[1]), "=r"(f[2]), "=r"(f[3]) : "r"(addr));
}
__device__ __forceinline__ void ldm_x4_t(uint32_t* f, uint32_t addr) {
    asm volatile("ldmatrix.sync.aligned.m8n8.x4.trans.shared.b16 {%0,%1,%2,%3}, [%4];"
                 : "=r"(f[0]), "=r"(f[1]), "=r"(f[2]), "=r"(f[3]) : "r"(addr));
}
__device__ __forceinline__ void mma_bf16(float* d, const uint32_t* a,
                                         uint32_t b0, uint32_t b1) {
    asm volatile("mma.sync.aligned.m16n8k16.row.col.f32.bf16.bf16.f32 "
                 "{%0,%1,%2,%3}, {%4,%5,%6,%7}, {%8,%9}, {%0,%1,%2,%3};"
                 : "+f"(d[0]), "+f"(d[1]), "+f"(d[2]), "+f"(d[3])
                 : "r"(a[0]), "r"(a[1]), "r"(a[2]), "r"(a[3]), "r"(b0), "r"(b1));
}
__device__ __forceinline__ void split_store(__nv_bfloat16* ph, __nv_bfloat16* pl,
                                            float2 v) {
    __nv_bfloat16 hx = __float2bfloat16(v.x), hy = __float2bfloat16(v.y);
    *reinterpret_cast<__nv_bfloat162*>(ph) = __halves2bfloat162(hx, hy);
    *reinterpret_cast<__nv_bfloat162*>(pl) = __halves2bfloat162(
        __float2bfloat16(v.x - __bfloat162float(hx)),
        __float2bfloat16(v.y - __bfloat162float(hy)));
}

// ---------------------------------------------------------------------------
// Conversion kernels
// ---------------------------------------------------------------------------
__global__ __launch_bounds__(256) void convert_rm(
    const float* __restrict__ in, __nv_bfloat16* __restrict__ oh,
    __nv_bfloat16* __restrict__ ol, size_t n)
{
    size_t i = ((size_t)blockIdx.x * 256 + threadIdx.x) * 4;
    if (i >= n) return;
    float4 v = *reinterpret_cast<const float4*>(in + i);
    split_store(oh + i, ol + i, make_float2(v.x, v.y));
    split_store(oh + i + 2, ol + i + 2, make_float2(v.z, v.w));
}

__global__ __launch_bounds__(256) void convert_transpose(
    const float* __restrict__ in, __nv_bfloat16* __restrict__ oh,
    __nv_bfloat16* __restrict__ ol, int R, int C)
{
    __shared__ float t[32][33];
    const int c0 = blockIdx.x * 32, r0 = blockIdx.y * 32;
    const int tx = threadIdx.x & 31, ty = threadIdx.x >> 5;
    #pragma unroll
    for (int i = 0; i < 32; i += 8)
        t[ty + i][tx] = in[(size_t)(r0 + ty + i) * C + c0 + tx];
    __syncthreads();
    #pragma unroll
    for (int i = 0; i < 32; i += 8) {
        float v = t[tx][ty + i];
        __nv_bfloat16 h = __float2bfloat16(v);
        oh[(size_t)(c0 + ty + i) * R + r0 + tx] = h;
        ol[(size_t)(c0 + ty + i) * R + r0 + tx] =
            __float2bfloat16(v - __bfloat162float(h));
    }
}

// ---------------------------------------------------------------------------
// mma.sync bf16x3 GEMM, CTA 128x128, 8 warps 32x64, K-chunk 32, cp.async x2.
// (256,2) -> <=128 regs -> 2 CTAs/SM. Term-major MMA ordering (reuse dist 4).
// mode 0: QKV epilogue -> bf16 hi/lo q/k/v; mode 1: fp32+bias -> Cout.
// ---------------------------------------------------------------------------
#define ROWB 80
#define TILEB (128 * ROWB)
#define STG_BYTES (4 * TILEB)
#define GEMM_SMEM (2 * STG_BYTES)

__global__ __launch_bounds__(256, 2) void gemm_mma_bf16x3(
    const __nv_bfloat16* __restrict__ Ah, const __nv_bfloat16* __restrict__ Al,
    const __nv_bfloat16* __restrict__ Bh, const __nv_bfloat16* __restrict__ Bl,
    const float* __restrict__ bias, float* __restrict__ Cout,
    int Kdim, int Ncols, int mode)
{
    extern __shared__ char smem[];
    const uint32_t sb = smem_u32(smem);
    const int tid = threadIdx.x;
    const int lane = tid & 31;
    const int wid = tid >> 5;
    const int wm = wid & 3;
    const int wn = wid >> 2;
    const int block_row = blockIdx.y * 128;
    const int block_col = blockIdx.x * 128;

    const __nv_bfloat16* srcs[4] = {
        Ah + (size_t)block_row * Kdim, Al + (size_t)block_row * Kdim,
        Bh + (size_t)block_col * Kdim, Bl + (size_t)block_col * Kdim};

    float acc[2][8][4];
    #pragma unroll
    for (int i = 0; i < 2; i++)
        #pragma unroll
        for (int j = 0; j < 8; j++)
            #pragma unroll
            for (int q = 0; q < 4; q++) acc[i][j][q] = 0.0f;

    const int nch = Kdim / 32;

    auto issue = [&](int c) {
        const int k0 = c * 32;
        const uint32_t stage = sb + (uint32_t)(c & 1) * STG_BYTES;
        #pragma unroll
        for (int t = 0; t < 8; t++) {
            int idx = tid + t * 256;
            int tile = idx >> 9;
            int r = (idx >> 2) & 127;
            int ch = idx & 3;
            const __nv_bfloat16* g = srcs[tile] + (size_t)r * Kdim + k0 + ch * 8;
            cp16(stage + (uint32_t)tile * TILEB + (uint32_t)r * ROWB + ch * 16, g);
        }
        asm volatile("cp.async.commit_group;");
    };

    issue(0);

    const int g8 = lane >> 3;
    const int r8 = lane & 7;

    for (int c = 0; c < nch; c++) {
        asm volatile("cp.async.wait_group 0;");
        __syncthreads();
        if (c + 1 < nch) issue(c + 1);
        const uint32_t stage = sb + (uint32_t)(c & 1) * STG_BYTES;

        #pragma unroll
        for (int kk = 0; kk < 2; kk++) {
            uint32_t ah[2][4], al[2][4];
            #pragma unroll
            for (int i = 0; i < 2; i++) {
                uint32_t row = wm * 32 + i * 16 + r8 + ((g8 & 1) << 3);
                uint32_t colb = kk * 32 + ((g8 >> 1) << 4);
                uint32_t a = stage + row * ROWB + colb;
                ldm_x4(ah[i], a);
                ldm_x4(al[i], a + TILEB);
            }
            #pragma unroll
            for (int jj = 0; jj < 4; jj++) {
                uint32_t nrow = wn * 64 + jj * 16 + r8 + ((g8 >> 1) << 3);
                uint32_t colb = kk * 32 + ((g8 & 1) << 4);
                uint32_t bptr = stage + 2 * TILEB + nrow * ROWB + colb;
                uint32_t bh[4], bl[4];
                ldm_x4(bh, bptr);
                ldm_x4(bl, bptr + TILEB);
                // term-major: 4 independent accs between reuses
                mma_bf16(acc[0][2 * jj + 0], ah[0], bh[0], bh[1]);
                mma_bf16(acc[0][2 * jj + 1], ah[0], bh[2], bh[3]);
                mma_bf16(acc[1][2 * jj + 0], ah[1], bh[0], bh[1]);
                mma_bf16(acc[1][2 * jj + 1], ah[1], bh[2], bh[3]);
                mma_bf16(acc[0][2 * jj + 0], ah[0], bl[0], bl[1]);
                mma_bf16(acc[0][2 * jj + 1], ah[0], bl[2], bl[3]);
                mma_bf16(acc[1][2 * jj + 0], ah[1], bl[0], bl[1]);
                mma_bf16(acc[1][2 * jj + 1], ah[1], bl[2], bl[3]);
                mma_bf16(acc[0][2 * jj + 0], al[0], bh[0], bh[1]);
                mma_bf16(acc[0][2 * jj + 1], al[0], bh[2], bh[3]);
                mma_bf16(acc[1][2 * jj + 0], al[1], bh[0], bh[1]);
                mma_bf16(acc[1][2 * jj + 1], al[1], bh[2], bh[3]);
            }
        }
        __syncthreads();
    }

    #pragma unroll
    for (int i = 0; i < 2; i++) {
        #pragma unroll
        for (int j = 0; j < 8; j++) {
            const int r0 = block_row + wm * 32 + i * 16 + (lane >> 2);
            const int n0 = block_col + wn * 64 + j * 8 + (lane & 3) * 2;
            const float bx = bias[n0], by = bias[n0 + 1];
            float2 lo = make_float2(acc[i][j][0] + bx, acc[i][j][1] + by);
            float2 hi = make_float2(acc[i][j][2] + bx, acc[i][j][3] + by);
            if (mode == 1) {
                *reinterpret_cast<float2*>(Cout + (size_t)r0 * Ncols + n0) = lo;
                *reinterpret_cast<float2*>(Cout + (size_t)(r0 + 8) * Ncols + n0) = hi;
            } else {
                const int part = n0 >> 10;
                const int within = n0 & (D_ - 1);
                const int h = within >> 6;
                const int hd = within & 63;
                __nv_bfloat16* bh_ = (part == 0 ? g_qh : part == 1 ? g_kh : g_vh);
                __nv_bfloat16* bl_ = (part == 0 ? g_ql : part == 1 ? g_kl : g_vl);
                const int b0r = r0 >> 10, s0 = r0 & (S_ - 1);
                size_t off0 = ((size_t)((b0r << 4) + h) * S_ + s0) * HD_ + hd;
                split_store(bh_ + off0, bl_ + off0, lo);
                const int r1 = r0 + 8;
                const int b1r = r1 >> 10, s1 = r1 & (S_ - 1);
                size_t off1 = ((size_t)((b1r << 4) + h) * S_ + s1) * HD_ + hd;
                split_store(bh_ + off1, bl_ + off1, hi);
            }
        }
    }
}

// ---------------------------------------------------------------------------
// Scores via HMMA bf16x3: per (head, lower-tri 128x128 tile). One-shot K=64.
// (256,2): 73KB smem -> 2 CTAs/SM. Term-major MMA ordering.
// ---------------------------------------------------------------------------
#define ROW2 144
#define STILE (128 * ROW2)     // 18432
#define SC_SMEM (4 * STILE)    // 73728

__global__ __launch_bounds__(256, 2) void scores_mma(float* __restrict__ w_out)
{
    extern __shared__ char smem[];
    const uint32_t sb = smem_u32(smem);
    const int head = blockIdx.y;
    int t = blockIdx.x, qb = 0;
    while (t >= qb + 1) { t -= qb + 1; qb++; }
    const int kb = t;

    const int tid = threadIdx.x;
    const int lane = tid & 31;
    const int wid = tid >> 5;
    const int wm = wid & 3;
    const int wn = wid >> 2;
    const int g8 = lane >> 3;
    const int r8 = lane & 7;

    const __nv_bfloat16* srcs[4] = {
        g_qh + ((size_t)head * S_ + qb * 128) * HD_,
        g_ql + ((size_t)head * S_ + qb * 128) * HD_,
        g_kh + ((size_t)head * S_ + kb * 128) * HD_,
        g_kl + ((size_t)head * S_ + kb * 128) * HD_};

    #pragma unroll
    for (int tt = 0; tt < 16; tt++) {
        int idx = tid + tt * 256;
        int tile = idx >> 10;
        int r = (idx >> 3) & 127;
        int ch = idx & 7;
        cp16(sb + (uint32_t)tile * STILE + (uint32_t)r * ROW2 + ch * 16,
             srcs[tile] + (size_t)r * HD_ + ch * 8);
    }
    asm volatile("cp.async.commit_group;");
    asm volatile("cp.async.wait_group 0;");
    __syncthreads();

    float acc[2][8][4];
    #pragma unroll
    for (int i = 0; i < 2; i++)
        #pragma unroll
        for (int j = 0; j < 8; j++)
            #pragma unroll
            for (int q = 0; q < 4; q++) acc[i][j][q] = 0.0f;

    #pragma unroll
    for (int kk = 0; kk < 4; kk++) {
        uint32_t ah[2][4], al[2][4];
        #pragma unroll
        for (int i = 0; i < 2; i++) {
            uint32_t row = wm * 32 + i * 16 + r8 + ((g8 & 1) << 3);
            uint32_t colb = kk * 32 + ((g8 >> 1) << 4);
            uint32_t a = sb + row * ROW2 + colb;
            ldm_x4(ah[i], a);
            ldm_x4(al[i], a + STILE);
        }
        #pragma unroll
        for (int jj = 0; jj < 4; jj++) {
            uint32_t nrow = wn * 64 + jj * 16 + r8 + ((g8 >> 1) << 3);
            uint32_t colb = kk * 32 + ((g8 & 1) << 4);
            uint32_t bptr = sb + 2 * STILE + nrow * ROW2 + colb;
            uint32_t bh[4], bl[4];
            ldm_x4(bh, bptr);
            ldm_x4(bl, bptr + STILE);
            mma_bf16(acc[0][2 * jj + 0], ah[0], bh[0], bh[1]);
            mma_bf16(acc[0][2 * jj + 1], ah[0], bh[2], bh[3]);
            mma_bf16(acc[1][2 * jj + 0], ah[1], bh[0], bh[1]);
            mma_bf16(acc[1][2 * jj + 1], ah[1], bh[2], bh[3]);
            mma_bf16(acc[0][2 * jj + 0], ah[0], bl[0], bl[1]);
            mma_bf16(acc[0][2 * jj + 1], ah[0], bl[2], bl[3]);
            mma_bf16(acc[1][2 * jj + 0], ah[1], bl[0], bl[1]);
            mma_bf16(acc[1][2 * jj + 1], ah[1], bl[2], bl[3]);
            mma_bf16(acc[0][2 * jj + 0], al[0], bh[0], bh[1]);
            mma_bf16(acc[0][2 * jj + 1], al[0], bh[2], bh[3]);
            mma_bf16(acc[1][2 * jj + 0], al[1], bh[0], bh[1]);
            mma_bf16(acc[1][2 * jj + 1], al[1], bh[2], bh[3]);
        }
    }

    const bool diag = (qb == kb);
    #pragma unroll
    for (int i = 0; i < 2; i++) {
        #pragma unroll
        for (int j = 0; j < 8; j++) {
            const int qi0 = qb * 128 + wm * 32 + i * 16 + (lane >> 2);
            const int kj = kb * 128 + wn * 64 + j * 8 + (lane & 3) * 2;
            float2 lo = make_float2(acc[i][j][0] * 0.125f, acc[i][j][1] * 0.125f);
            float2 hi = make_float2(acc[i][j][2] * 0.125f, acc[i][j][3] * 0.125f);
            if (diag) {
                if (kj + 0 > qi0) lo.x = -NEG_;
                if (kj + 1 > qi0) lo.y = -NEG_;
                if (kj + 0 > qi0 + 8) hi.x = -NEG_;
                if (kj + 1 > qi0 + 8) hi.y = -NEG_;
            }
            *reinterpret_cast<float2*>(
                w_out + ((size_t)head * S_ + qi0) * S_ + kj) = lo;
            *reinterpret_cast<float2*>(
                w_out + ((size_t)head * S_ + qi0 + 8) * S_ + kj) = hi;
        }
    }
}

// ---------------------------------------------------------------------------
// Softmax: 256 threads per row, register float4. Writes fp32 probs to w_out
// and bf16 hi/lo probs to g_ph/g_pl (valid prefix only).
// ---------------------------------------------------------------------------
__global__ __launch_bounds__(256) void softmax_kernel(
    const float* __restrict__ mask, float* __restrict__ w_out)
{
    const int idx = blockIdx.x;        // head*S + qi
    const int qi = idx & (S_ - 1);
    const int head = idx >> 10;
    const int b = head >> 4;
    const int tid = threadIdx.x;
    const int j0 = tid * 4;
    const int valid = ((qi >> 7) + 1) << 7;

    __shared__ float redm[8], reds[8];

    float* wrow = w_out + (size_t)idx * S_;
    const float* mrow = mask + b * S_;

    float4 s4;
    if (j0 < valid) s4 = *reinterpret_cast<const float4*>(wrow + j0);
    else            s4 = make_float4(-NEG_, -NEG_, -NEG_, -NEG_);
    float4 m4 = *reinterpret_cast<const float4*>(mrow + j0);
    s4.x += m4.x; s4.y += m4.y; s4.z += m4.z; s4.w += m4.w;

    float m = fmaxf(fmaxf(s4.x, s4.y), fmaxf(s4.z, s4.w));
    #pragma unroll
    for (int o = 16; o; o >>= 1) m = fmaxf(m, __shfl_xor_sync(0xffffffffu, m, o));
    if ((tid & 31) == 0) redm[tid >> 5] = m;
    __syncthreads();
    #pragma unroll
    for (int w = 0; w < 8; w++) m = fmaxf(m, redm[w]);

    float4 e4;
    e4.x = __expf(s4.x - m); e4.y = __expf(s4.y - m);
    e4.z = __expf(s4.z - m); e4.w = __expf(s4.w - m);
    float lsum = e4.x + e4.y + e4.z + e4.w;
    #pragma unroll
    for (int o = 16; o; o >>= 1) lsum += __shfl_xor_sync(0xffffffffu, lsum, o);
    if ((tid & 31) == 0) reds[tid >> 5] = lsum;
    __syncthreads();
    float total = 0.0f;
    #pragma unroll
    for (int w = 0; w < 8; w++) total += reds[w];
    const float inv = 1.0f / total;

    float4 p4;
    p4.x = e4.x * inv; p4.y = e4.y * inv; p4.z = e4.z * inv; p4.w = e4.w * inv;
    *reinterpret_cast<float4*>(wrow + j0) = p4;

    if (j0 < valid) {
        size_t off = (size_t)idx * S_ + j0;
        split_store(g_ph + off,     g_pl + off,     make_float2(p4.x, p4.y));
        split_store(g_ph + off + 2, g_pl + off + 2, make_float2(p4.z, p4.w));
    }
}

// ---------------------------------------------------------------------------
// AV via HMMA bf16x3: per (head, qb). M=128, N=64, K=kmax. V via trans-ldm.
// Term-major MMA ordering.
// ---------------------------------------------------------------------------
#define AV_P  18432              // P tile bytes (128 x 144)
#define AV_V  9216               // V tile bytes (64 x 144)
#define AV_STG (2 * AV_P + 2 * AV_V)   // 55296
#define AV_SMEM (2 * AV_STG)           // 110592

__global__ __launch_bounds__(256, 2) void av_mma()
{
    extern __shared__ char smem[];
    const uint32_t sb = smem_u32(smem);
    const int head = blockIdx.y;
    const int qb = 7 - blockIdx.x;     // big tiles first
    const int b = head >> 4;
    const int h = head & 15;

    const int tid = threadIdx.x;
    const int lane = tid & 31;
    const int wid = tid >> 5;
    const int wm = wid & 3;
    const int wn = wid >> 2;
    const int g8 = lane >> 3;
    const int r8 = lane & 7;

    const __nv_bfloat16* Phb = g_ph + ((size_t)head * S_ + qb * 128) * S_;
    const __nv_bfloat16* Plb = g_pl + ((size_t)head * S_ + qb * 128) * S_;
    const __nv_bfloat16* Vhb = g_vh + (size_t)head * S_ * HD_;
    const __nv_bfloat16* Vlb = g_vl + (size_t)head * S_ * HD_;

    const int nch = 2 * (qb + 1);      // K-chunks of 64

    auto issue = [&](int c) {
        const int k0 = c * 64;
        const uint32_t stage = sb + (uint32_t)(c & 1) * AV_STG;
        #pragma unroll
        for (int t = 0; t < 12; t++) {
            int idx = tid + t * 256;
            if (idx < 2048) {
                int tile = idx >> 10;              // 0 Ph, 1 Pl
                int r = (idx >> 3) & 127;
                int ch = idx & 7;
                const __nv_bfloat16* g = (tile ? Plb : Phb) + (size_t)r * S_ + k0 + ch * 8;
                cp16(stage + (uint32_t)tile * AV_P + (uint32_t)r * ROW2 + ch * 16, g);
            } else {
                int v = idx - 2048;
                int tile = v >> 9;                 // 0 Vh, 1 Vl
                int r = (v >> 3) & 63;
                int ch = v & 7;
                const __nv_bfloat16* g = (tile ? Vlb : Vhb) + (size_t)(k0 + r) * HD_ + ch * 8;
                cp16(stage + 2 * AV_P + (uint32_t)tile * AV_V + (uint32_t)r * ROW2 + ch * 16, g);
            }
        }
        asm volatile("cp.async.commit_group;");
    };

    float acc[2][4][4];
    #pragma unroll
    for (int i = 0; i < 2; i++)
        #pragma unroll
        for (int j = 0; j < 4; j++)
            #pragma unroll
            for (int q = 0; q < 4; q++) acc[i][j][q] = 0.0f;

    issue(0);
    for (int c = 0; c < nch; c++) {
        if (c + 1 < nch) {
            issue(c + 1);
            asm volatile("cp.async.wait_group 1;");
        } else {
            asm volatile("cp.async.wait_group 0;");
        }
        __syncthreads();
        const uint32_t stage = sb + (uint32_t)(c & 1) * AV_STG;

        #pragma unroll
        for (int kk = 0; kk < 4; kk++) {
            uint32_t ph[2][4], pl[2][4];
            #pragma unroll
            for (int i = 0; i < 2; i++) {
                uint32_t row = wm * 32 + i * 16 + r8 + ((g8 & 1) << 3);
                uint32_t colb = kk * 32 + ((g8 >> 1) << 4);
                uint32_t a = stage + row * ROW2 + colb;
                ldm_x4(ph[i], a);
                ldm_x4(pl[i], a + AV_P);
            }
            #pragma unroll
            for (int jj = 0; jj < 2; jj++) {
                uint32_t row = kk * 16 + r8 + ((g8 & 1) << 3);
                uint32_t colb = (wn * 32 + jj * 16 + ((g8 >> 1) << 3)) * 2;
                uint32_t bptr = stage + 2 * AV_P + row * ROW2 + colb;
                uint32_t bh[4], bl[4];
                ldm_x4_t(bh, bptr);
                ldm_x4_t(bl, bptr + AV_V);
                mma_bf16(acc[0][2 * jj + 0], ph[0], bh[0], bh[1]);
                mma_bf16(acc[0][2 * jj + 1], ph[0], bh[2], bh[3]);
                mma_bf16(acc[1][2 * jj + 0], ph[1], bh[0], bh[1]);
                mma_bf16(acc[1][2 * jj + 1], ph[1], bh[2], bh[3]);
                mma_bf16(acc[0][2 * jj + 0], ph[0], bl[0], bl[1]);
                mma_bf16(acc[0][2 * jj + 1], ph[0], bl[2], bl[3]);
                mma_bf16(acc[1][2 * jj + 0], ph[1], bl[0], bl[1]);
                mma_bf16(acc[1][2 * jj + 1], ph[1], bl[2], bl[3]);
                mma_bf16(acc[0][2 * jj + 0], pl[0], bh[0], bh[1]);
                mma_bf16(acc[0][2 * jj + 1], pl[0], bh[2], bh[3]);
                mma_bf16(acc[1][2 * jj + 0], pl[1], bh[0], bh[1]);
                mma_bf16(acc[1][2 * jj + 1], pl[1], bh[2], bh[3]);
            }
        }
        __syncthreads();
    }

    // epilogue -> ctx bf16 hi/lo at [b*S+s, h*64+d]
    #pragma unroll
    for (int i = 0; i < 2; i++) {
        #pragma unroll
        for (int j = 0; j < 4; j++) {
            const int s0 = qb * 128 + wm * 32 + i * 16 + (lane >> 2);
            const int d0 = wn * 32 + j * 8 + (lane & 3) * 2;
            float2 lo = make_float2(acc[i][j][0], acc[i][j][1]);
            float2 hi = make_float2(acc[i][j][2], acc[i][j][3]);
            size_t off0 = (size_t)(b * S_ + s0) * D_ + h * HD_ + d0;
            split_store(g_ch + off0, g_cl + off0, lo);
            size_t off1 = (size_t)(b * S_ + s0 + 8) * D_ + h * HD_ + d0;
            split_store(g_ch + off1, g_cl + off1, hi);
        }
    }
}

// ---------------------------------------------------------------------------
extern "C" void kernel_launch(void* const* d_in, const int* in_sizes, int n_in,
                              void* d_out, int out_size)
{
    const float* x      = (const float*)d_in[0];
    const float* mask   = (const float*)d_in[1];
    const float* w_attn = (const float*)d_in[2];
    const float* b_attn = (const float*)d_in[3];
    const float* w_proj = (const float*)d_in[4];
    const float* b_proj = (const float*)d_in[5];

    float* out   = (float*)d_out;
    float* a_out = out;                         // [B,S,D]
    float* w_out = out + (size_t)M_ * D_;       // [B,H,S,S]

    __nv_bfloat16 *xh, *xl, *wah, *wal, *wph, *wpl, *ch, *cl;
    cudaGetSymbolAddress((void**)&xh,  g_xh);
    cudaGetSymbolAddress((void**)&xl,  g_xl);
    cudaGetSymbolAddress((void**)&wah, g_wah);
    cudaGetSymbolAddress((void**)&wal, g_wal);
    cudaGetSymbolAddress((void**)&wph, g_wph);
    cudaGetSymbolAddress((void**)&wpl, g_wpl);
    cudaGetSymbolAddress((void**)&ch,  g_ch);
    cudaGetSymbolAddress((void**)&cl,  g_cl);

    cudaFuncSetAttribute(gemm_mma_bf16x3,
                         cudaFuncAttributeMaxDynamicSharedMemorySize, GEMM_SMEM);
    cudaFuncSetAttribute(scores_mma,
                         cudaFuncAttributeMaxDynamicSharedMemorySize, SC_SMEM);
    cudaFuncSetAttribute(av_mma,
                         cudaFuncAttributeMaxDynamicSharedMemorySize, AV_SMEM);

    // 1) converts
    convert_rm<<<(M_ * D_ / 4 + 255) / 256, 256>>>(x, xh, xl, (size_t)M_ * D_);
    convert_transpose<<<dim3(TD_ / 32, D_ / 32), 256>>>(w_attn, wah, wal, D_, TD_);
    convert_transpose<<<dim3(D_ / 32, D_ / 32), 256>>>(w_proj, wph, wpl, D_, D_);

    // 2) QKV GEMM -> bf16 hi/lo q/k/v
    gemm_mma_bf16x3<<<dim3(TD_ / 128, M_ / 128), 256, GEMM_SMEM>>>(
        xh, xl, wah, wal, b_attn, nullptr, D_, TD_, 0);

    // 3) Scores (HMMA, lower-tri) -> softmax (emits bf16 P) -> AV (HMMA)
    scores_mma<<<dim3(36, NH_), 256, SC_SMEM>>>(w_out);
    softmax_kernel<<<NH_ * S_, 256>>>(mask, w_out);
    av_mma<<<dim3(8, NH_), 256, AV_SMEM>>>();

    // 4) Output projection
    gemm_mma_bf16x3<<<dim3(D_ / 128, M_ / 128), 256, GEMM_SMEM>>>(
        ch, cl, wph, wpl, b_proj, a_out, D_, D_, 1);
}

// round 13
// speedup vs baseline: 1.0400x; 1.0400x over previous
#include <cuda_runtime.h>
#include <cuda_bf16.h>
#include <cstdint>

#define B_  4
#define S_  1024
#define D_  1024
#define H_  16
#define HD_ 64
#define M_  (B_ * S_)        // 4096 rows
#define TD_ (3 * D_)         // 3072
#define NH_ (B_ * H_)        // 64 head-batches
#define NEG_ 10000.0f

// ---------------------------------------------------------------------------
// Scratch (allocation-free rule: __device__ globals)
// ---------------------------------------------------------------------------
__device__ __nv_bfloat16 g_qh[(size_t)NH_ * S_ * HD_];  // [head, s, 64]
__device__ __nv_bfloat16 g_ql[(size_t)NH_ * S_ * HD_];
__device__ __nv_bfloat16 g_kh[(size_t)NH_ * S_ * HD_];
__device__ __nv_bfloat16 g_kl[(size_t)NH_ * S_ * HD_];
__device__ __nv_bfloat16 g_vh[(size_t)NH_ * S_ * HD_];
__device__ __nv_bfloat16 g_vl[(size_t)NH_ * S_ * HD_];
__device__ __nv_bfloat16 g_ph[(size_t)NH_ * S_ * S_];   // probs hi/lo
__device__ __nv_bfloat16 g_pl[(size_t)NH_ * S_ * S_];
__device__ __nv_bfloat16 g_ch[(size_t)M_ * D_];          // ctx hi/lo row-major
__device__ __nv_bfloat16 g_cl[(size_t)M_ * D_];

__device__ __nv_bfloat16 g_xh[(size_t)M_ * D_];          // x hi/lo row-major
__device__ __nv_bfloat16 g_xl[(size_t)M_ * D_];
__device__ __nv_bfloat16 g_wah[(size_t)TD_ * D_];        // w_attn^T hi/lo
__device__ __nv_bfloat16 g_wal[(size_t)TD_ * D_];
__device__ __nv_bfloat16 g_wph[(size_t)D_ * D_];         // w_proj^T hi/lo
__device__ __nv_bfloat16 g_wpl[(size_t)D_ * D_];

__device__ __forceinline__ uint32_t smem_u32(const void* p) {
    uint32_t a;
    asm("{ .reg .u64 t; cvta.to.shared.u64 t, %1; cvt.u32.u64 %0, t; }" : "=r"(a) : "l"(p));
    return a;
}
__device__ __forceinline__ void cp16(uint32_t s, const void* g) {
    asm volatile("cp.async.ca.shared.global [%0], [%1], 16;" :: "r"(s), "l"(g));
}
__device__ __forceinline__ void ldm_x4(uint32_t* f, uint32_t addr) {
    asm volatile("ldmatrix.sync.aligned.m8n8.x4.shared.b16 {%0,%1,%2,%3}, [%4];"
                 : "=r"(f[0]), "=r"(f[1]), "=r"(f[2]), "=r"(f[3]) : "r"(addr));
}
__device__ __forceinline__ void ldm_x4_t(uint32_t* f, uint32_t addr) {
    asm volatile("ldmatrix.sync.aligned.m8n8.x4.trans.shared.b16 {%0,%1,%2,%3}, [%4];"
                 : "=r"(f[0]), "=r"(f[1]), "=r"(f[2]), "=r"(f[3]) : "r"(addr));
}
__device__ __forceinline__ void mma_bf16(float* d, const uint32_t* a,
                                         uint32_t b0, uint32_t b1) {
    asm volatile("mma.sync.aligned.m16n8k16.row.col.f32.bf16.bf16.f32 "
                 "{%0,%1,%2,%3}, {%4,%5,%6,%7}, {%8,%9}, {%0,%1,%2,%3};"
                 : "+f"(d[0]), "+f"(d[1]), "+f"(d[2]), "+f"(d[3])
                 : "r"(a[0]), "r"(a[1]), "r"(a[2]), "r"(a[3]), "r"(b0), "r"(b1));
}
__device__ __forceinline__ void split_store(__nv_bfloat16* ph, __nv_bfloat16* pl,
                                            float2 v) {
    __nv_bfloat16 hx = __float2bfloat16(v.x), hy = __float2bfloat16(v.y);
    *reinterpret_cast<__nv_bfloat162*>(ph) = __halves2bfloat162(hx, hy);
    *reinterpret_cast<__nv_bfloat162*>(pl) = __halves2bfloat162(
        __float2bfloat16(v.x - __bfloat162float(hx)),
        __float2bfloat16(v.y - __bfloat162float(hy)));
}

// ---------------------------------------------------------------------------
// Conversion kernels
// ---------------------------------------------------------------------------
__global__ __launch_bounds__(256) void convert_rm(
    const float* __restrict__ in, __nv_bfloat16* __restrict__ oh,
    __nv_bfloat16* __restrict__ ol, size_t n)
{
    size_t i = ((size_t)blockIdx.x * 256 + threadIdx.x) * 4;
    if (i >= n) return;
    float4 v = *reinterpret_cast<const float4*>(in + i);
    split_store(oh + i, ol + i, make_float2(v.x, v.y));
    split_store(oh + i + 2, ol + i + 2, make_float2(v.z, v.w));
}

__global__ __launch_bounds__(256) void convert_transpose(
    const float* __restrict__ in, __nv_bfloat16* __restrict__ oh,
    __nv_bfloat16* __restrict__ ol, int R, int C)
{
    __shared__ float t[32][33];
    const int c0 = blockIdx.x * 32, r0 = blockIdx.y * 32;
    const int tx = threadIdx.x & 31, ty = threadIdx.x >> 5;
    #pragma unroll
    for (int i = 0; i < 32; i += 8)
        t[ty + i][tx] = in[(size_t)(r0 + ty + i) * C + c0 + tx];
    __syncthreads();
    #pragma unroll
    for (int i = 0; i < 32; i += 8) {
        float v = t[tx][ty + i];
        __nv_bfloat16 h = __float2bfloat16(v);
        oh[(size_t)(c0 + ty + i) * R + r0 + tx] = h;
        ol[(size_t)(c0 + ty + i) * R + r0 + tx] =
            __float2bfloat16(v - __bfloat162float(h));
    }
}

// ---------------------------------------------------------------------------
// mma.sync bf16x3 GEMM, CTA 128x128, *4 warps of 64x64*, K-chunk 32,
// cp.async x2. (128,2): 256-reg budget, 2 CTAs/SM.
// 64x64 warp tile: 1.5x fewer smem bytes per MMA (smem-BW bound fix).
// mode 0: QKV epilogue -> bf16 hi/lo q/k/v; mode 1: fp32+bias -> Cout.
// ---------------------------------------------------------------------------
#define ROWB 80
#define TILEB (128 * ROWB)
#define STG_BYTES (4 * TILEB)
#define GEMM_SMEM (2 * STG_BYTES)

__global__ __launch_bounds__(128, 2) void gemm_mma_bf16x3(
    const __nv_bfloat16* __restrict__ Ah, const __nv_bfloat16* __restrict__ Al,
    const __nv_bfloat16* __restrict__ Bh, const __nv_bfloat16* __restrict__ Bl,
    const float* __restrict__ bias, float* __restrict__ Cout,
    int Kdim, int Ncols, int mode)
{
    extern __shared__ char smem[];
    const uint32_t sb = smem_u32(smem);
    const int tid = threadIdx.x;
    const int lane = tid & 31;
    const int wid = tid >> 5;         // 0..3
    const int wm = wid & 1;           // warp row: 64*wm
    const int wn = wid >> 1;          // warp col: 64*wn
    const int block_row = blockIdx.y * 128;
    const int block_col = blockIdx.x * 128;

    const __nv_bfloat16* srcs[4] = {
        Ah + (size_t)block_row * Kdim, Al + (size_t)block_row * Kdim,
        Bh + (size_t)block_col * Kdim, Bl + (size_t)block_col * Kdim};

    float acc[4][8][4];
    #pragma unroll
    for (int i = 0; i < 4; i++)
        #pragma unroll
        for (int j = 0; j < 8; j++)
            #pragma unroll
            for (int q = 0; q < 4; q++) acc[i][j][q] = 0.0f;

    const int nch = Kdim / 32;

    auto issue = [&](int c) {
        const int k0 = c * 32;
        const uint32_t stage = sb + (uint32_t)(c & 1) * STG_BYTES;
        #pragma unroll
        for (int t = 0; t < 16; t++) {
            int idx = tid + t * 128;
            int tile = idx >> 9;
            int r = (idx >> 2) & 127;
            int ch = idx & 3;
            const __nv_bfloat16* g = srcs[tile] + (size_t)r * Kdim + k0 + ch * 8;
            cp16(stage + (uint32_t)tile * TILEB + (uint32_t)r * ROWB + ch * 16, g);
        }
        asm volatile("cp.async.commit_group;");
    };

    issue(0);

    const int g8 = lane >> 3;
    const int r8 = lane & 7;

    for (int c = 0; c < nch; c++) {
        asm volatile("cp.async.wait_group 0;");
        __syncthreads();
        if (c + 1 < nch) issue(c + 1);
        const uint32_t stage = sb + (uint32_t)(c & 1) * STG_BYTES;

        #pragma unroll
        for (int kk = 0; kk < 2; kk++) {
            uint32_t ah[4][4], al[4][4];
            #pragma unroll
            for (int i = 0; i < 4; i++) {
                uint32_t row = wm * 64 + i * 16 + r8 + ((g8 & 1) << 3);
                uint32_t colb = kk * 32 + ((g8 >> 1) << 4);
                uint32_t a = stage + row * ROWB + colb;
                ldm_x4(ah[i], a);
                ldm_x4(al[i], a + TILEB);
            }
            #pragma unroll
            for (int jj = 0; jj < 4; jj++) {
                uint32_t nrow = wn * 64 + jj * 16 + r8 + ((g8 >> 1) << 3);
                uint32_t colb = kk * 32 + ((g8 & 1) << 4);
                uint32_t bptr = stage + 2 * TILEB + nrow * ROWB + colb;
                uint32_t bh[4], bl[4];
                ldm_x4(bh, bptr);
                ldm_x4(bl, bptr + TILEB);
                #pragma unroll
                for (int i = 0; i < 4; i++) {
                    mma_bf16(acc[i][2 * jj + 0], ah[i], bh[0], bh[1]);
                    mma_bf16(acc[i][2 * jj + 1], ah[i], bh[2], bh[3]);
                    mma_bf16(acc[i][2 * jj + 0], ah[i], bl[0], bl[1]);
                    mma_bf16(acc[i][2 * jj + 1], ah[i], bl[2], bl[3]);
                    mma_bf16(acc[i][2 * jj + 0], al[i], bh[0], bh[1]);
                    mma_bf16(acc[i][2 * jj + 1], al[i], bh[2], bh[3]);
                }
            }
        }
        __syncthreads();
    }

    #pragma unroll
    for (int i = 0; i < 4; i++) {
        #pragma unroll
        for (int j = 0; j < 8; j++) {
            const int r0 = block_row + wm * 64 + i * 16 + (lane >> 2);
            const int n0 = block_col + wn * 64 + j * 8 + (lane & 3) * 2;
            const float bx = bias[n0], by = bias[n0 + 1];
            float2 lo = make_float2(acc[i][j][0] + bx, acc[i][j][1] + by);
            float2 hi = make_float2(acc[i][j][2] + bx, acc[i][j][3] + by);
            if (mode == 1) {
                *reinterpret_cast<float2*>(Cout + (size_t)r0 * Ncols + n0) = lo;
                *reinterpret_cast<float2*>(Cout + (size_t)(r0 + 8) * Ncols + n0) = hi;
            } else {
                const int part = n0 >> 10;
                const int within = n0 & (D_ - 1);
                const int h = within >> 6;
                const int hd = within & 63;
                __nv_bfloat16* bh_ = (part == 0 ? g_qh : part == 1 ? g_kh : g_vh);
                __nv_bfloat16* bl_ = (part == 0 ? g_ql : part == 1 ? g_kl : g_vl);
                const int b0r = r0 >> 10, s0 = r0 & (S_ - 1);
                size_t off0 = ((size_t)((b0r << 4) + h) * S_ + s0) * HD_ + hd;
                split_store(bh_ + off0, bl_ + off0, lo);
                const int r1 = r0 + 8;
                const int b1r = r1 >> 10, s1 = r1 & (S_ - 1);
                size_t off1 = ((size_t)((b1r << 4) + h) * S_ + s1) * HD_ + hd;
                split_store(bh_ + off1, bl_ + off1, hi);
            }
        }
    }
}

// ---------------------------------------------------------------------------
// Scores via HMMA bf16x3: per (head, lower-tri 128x128 tile). One-shot K=64.
// (256,2): 73KB smem -> 2 CTAs/SM.
// ---------------------------------------------------------------------------
#define ROW2 144
#define STILE (128 * ROW2)     // 18432
#define SC_SMEM (4 * STILE)    // 73728

__global__ __launch_bounds__(256, 2) void scores_mma(float* __restrict__ w_out)
{
    extern __shared__ char smem[];
    const uint32_t sb = smem_u32(smem);
    const int head = blockIdx.y;
    int t = blockIdx.x, qb = 0;
    while (t >= qb + 1) { t -= qb + 1; qb++; }
    const int kb = t;

    const int tid = threadIdx.x;
    const int lane = tid & 31;
    const int wid = tid >> 5;
    const int wm = wid & 3;
    const int wn = wid >> 2;
    const int g8 = lane >> 3;
    const int r8 = lane & 7;

    const __nv_bfloat16* srcs[4] = {
        g_qh + ((size_t)head * S_ + qb * 128) * HD_,
        g_ql + ((size_t)head * S_ + qb * 128) * HD_,
        g_kh + ((size_t)head * S_ + kb * 128) * HD_,
        g_kl + ((size_t)head * S_ + kb * 128) * HD_};

    #pragma unroll
    for (int tt = 0; tt < 16; tt++) {
        int idx = tid + tt * 256;
        int tile = idx >> 10;
        int r = (idx >> 3) & 127;
        int ch = idx & 7;
        cp16(sb + (uint32_t)tile * STILE + (uint32_t)r * ROW2 + ch * 16,
             srcs[tile] + (size_t)r * HD_ + ch * 8);
    }
    asm volatile("cp.async.commit_group;");
    asm volatile("cp.async.wait_group 0;");
    __syncthreads();

    float acc[2][8][4];
    #pragma unroll
    for (int i = 0; i < 2; i++)
        #pragma unroll
        for (int j = 0; j < 8; j++)
            #pragma unroll
            for (int q = 0; q < 4; q++) acc[i][j][q] = 0.0f;

    #pragma unroll
    for (int kk = 0; kk < 4; kk++) {
        uint32_t ah[2][4], al[2][4];
        #pragma unroll
        for (int i = 0; i < 2; i++) {
            uint32_t row = wm * 32 + i * 16 + r8 + ((g8 & 1) << 3);
            uint32_t colb = kk * 32 + ((g8 >> 1) << 4);
            uint32_t a = sb + row * ROW2 + colb;
            ldm_x4(ah[i], a);
            ldm_x4(al[i], a + STILE);
        }
        #pragma unroll
        for (int jj = 0; jj < 4; jj++) {
            uint32_t nrow = wn * 64 + jj * 16 + r8 + ((g8 >> 1) << 3);
            uint32_t colb = kk * 32 + ((g8 & 1) << 4);
            uint32_t bptr = sb + 2 * STILE + nrow * ROW2 + colb;
            uint32_t bh[4], bl[4];
            ldm_x4(bh, bptr);
            ldm_x4(bl, bptr + STILE);
            #pragma unroll
            for (int i = 0; i < 2; i++) {
                mma_bf16(acc[i][2 * jj + 0], ah[i], bh[0], bh[1]);
                mma_bf16(acc[i][2 * jj + 1], ah[i], bh[2], bh[3]);
                mma_bf16(acc[i][2 * jj + 0], ah[i], bl[0], bl[1]);
                mma_bf16(acc[i][2 * jj + 1], ah[i], bl[2], bl[3]);
                mma_bf16(acc[i][2 * jj + 0], al[i], bh[0], bh[1]);
                mma_bf16(acc[i][2 * jj + 1], al[i], bh[2], bh[3]);
            }
        }
    }

    const bool diag = (qb == kb);
    #pragma unroll
    for (int i = 0; i < 2; i++) {
        #pragma unroll
        for (int j = 0; j < 8; j++) {
            const int qi0 = qb * 128 + wm * 32 + i * 16 + (lane >> 2);
            const int kj = kb * 128 + wn * 64 + j * 8 + (lane & 3) * 2;
            float2 lo = make_float2(acc[i][j][0] * 0.125f, acc[i][j][1] * 0.125f);
            float2 hi = make_float2(acc[i][j][2] * 0.125f, acc[i][j][3] * 0.125f);
            if (diag) {
                if (kj + 0 > qi0) lo.x = -NEG_;
                if (kj + 1 > qi0) lo.y = -NEG_;
                if (kj + 0 > qi0 + 8) hi.x = -NEG_;
                if (kj + 1 > qi0 + 8) hi.y = -NEG_;
            }
            *reinterpret_cast<float2*>(
                w_out + ((size_t)head * S_ + qi0) * S_ + kj) = lo;
            *reinterpret_cast<float2*>(
                w_out + ((size_t)head * S_ + qi0 + 8) * S_ + kj) = hi;
        }
    }
}

// ---------------------------------------------------------------------------
// Softmax: 256 threads per row, register float4. Writes fp32 probs to w_out
// and bf16 hi/lo probs to g_ph/g_pl (valid prefix only).
// ---------------------------------------------------------------------------
__global__ __launch_bounds__(256) void softmax_kernel(
    const float* __restrict__ mask, float* __restrict__ w_out)
{
    const int idx = blockIdx.x;        // head*S + qi
    const int qi = idx & (S_ - 1);
    const int head = idx >> 10;
    const int b = head >> 4;
    const int tid = threadIdx.x;
    const int j0 = tid * 4;
    const int valid = ((qi >> 7) + 1) << 7;

    __shared__ float redm[8], reds[8];

    float* wrow = w_out + (size_t)idx * S_;
    const float* mrow = mask + b * S_;

    float4 s4;
    if (j0 < valid) s4 = *reinterpret_cast<const float4*>(wrow + j0);
    else            s4 = make_float4(-NEG_, -NEG_, -NEG_, -NEG_);
    float4 m4 = *reinterpret_cast<const float4*>(mrow + j0);
    s4.x += m4.x; s4.y += m4.y; s4.z += m4.z; s4.w += m4.w;

    float m = fmaxf(fmaxf(s4.x, s4.y), fmaxf(s4.z, s4.w));
    #pragma unroll
    for (int o = 16; o; o >>= 1) m = fmaxf(m, __shfl_xor_sync(0xffffffffu, m, o));
    if ((tid & 31) == 0) redm[tid >> 5] = m;
    __syncthreads();
    #pragma unroll
    for (int w = 0; w < 8; w++) m = fmaxf(m, redm[w]);

    float4 e4;
    e4.x = __expf(s4.x - m); e4.y = __expf(s4.y - m);
    e4.z = __expf(s4.z - m); e4.w = __expf(s4.w - m);
    float lsum = e4.x + e4.y + e4.z + e4.w;
    #pragma unroll
    for (int o = 16; o; o >>= 1) lsum += __shfl_xor_sync(0xffffffffu, lsum, o);
    if ((tid & 31) == 0) reds[tid >> 5] = lsum;
    __syncthreads();
    float total = 0.0f;
    #pragma unroll
    for (int w = 0; w < 8; w++) total += reds[w];
    const float inv = 1.0f / total;

    float4 p4;
    p4.x = e4.x * inv; p4.y = e4.y * inv; p4.z = e4.z * inv; p4.w = e4.w * inv;
    *reinterpret_cast<float4*>(wrow + j0) = p4;

    if (j0 < valid) {
        size_t off = (size_t)idx * S_ + j0;
        split_store(g_ph + off,     g_pl + off,     make_float2(p4.x, p4.y));
        split_store(g_ph + off + 2, g_pl + off + 2, make_float2(p4.z, p4.w));
    }
}

// ---------------------------------------------------------------------------
// AV via HMMA bf16x3: per (head, qb). M=128, N=64, K=kmax. V via trans-ldm.
// ---------------------------------------------------------------------------
#define AV_P  18432              // P tile bytes (128 x 144)
#define AV_V  9216               // V tile bytes (64 x 144)
#define AV_STG (2 * AV_P + 2 * AV_V)   // 55296
#define AV_SMEM (2 * AV_STG)           // 110592

__global__ __launch_bounds__(256, 2) void av_mma()
{
    extern __shared__ char smem[];
    const uint32_t sb = smem_u32(smem);
    const int head = blockIdx.y;
    const int qb = 7 - blockIdx.x;     // big tiles first
    const int b = head >> 4;
    const int h = head & 15;

    const int tid = threadIdx.x;
    const int lane = tid & 31;
    const int wid = tid >> 5;
    const int wm = wid & 3;
    const int wn = wid >> 2;
    const int g8 = lane >> 3;
    const int r8 = lane & 7;

    const __nv_bfloat16* Phb = g_ph + ((size_t)head * S_ + qb * 128) * S_;
    const __nv_bfloat16* Plb = g_pl + ((size_t)head * S_ + qb * 128) * S_;
    const __nv_bfloat16* Vhb = g_vh + (size_t)head * S_ * HD_;
    const __nv_bfloat16* Vlb = g_vl + (size_t)head * S_ * HD_;

    const int nch = 2 * (qb + 1);      // K-chunks of 64

    auto issue = [&](int c) {
        const int k0 = c * 64;
        const uint32_t stage = sb + (uint32_t)(c & 1) * AV_STG;
        #pragma unroll
        for (int t = 0; t < 12; t++) {
            int idx = tid + t * 256;
            if (idx < 2048) {
                int tile = idx >> 10;              // 0 Ph, 1 Pl
                int r = (idx >> 3) & 127;
                int ch = idx & 7;
                const __nv_bfloat16* g = (tile ? Plb : Phb) + (size_t)r * S_ + k0 + ch * 8;
                cp16(stage + (uint32_t)tile * AV_P + (uint32_t)r * ROW2 + ch * 16, g);
            } else {
                int v = idx - 2048;
                int tile = v >> 9;                 // 0 Vh, 1 Vl
                int r = (v >> 3) & 63;
                int ch = v & 7;
                const __nv_bfloat16* g = (tile ? Vlb : Vhb) + (size_t)(k0 + r) * HD_ + ch * 8;
                cp16(stage + 2 * AV_P + (uint32_t)tile * AV_V + (uint32_t)r * ROW2 + ch * 16, g);
            }
        }
        asm volatile("cp.async.commit_group;");
    };

    float acc[2][4][4];
    #pragma unroll
    for (int i = 0; i < 2; i++)
        #pragma unroll
        for (int j = 0; j < 4; j++)
            #pragma unroll
            for (int q = 0; q < 4; q++) acc[i][j][q] = 0.0f;

    issue(0);
    for (int c = 0; c < nch; c++) {
        if (c + 1 < nch) {
            issue(c + 1);
            asm volatile("cp.async.wait_group 1;");
        } else {
            asm volatile("cp.async.wait_group 0;");
        }
        __syncthreads();
        const uint32_t stage = sb + (uint32_t)(c & 1) * AV_STG;

        #pragma unroll
        for (int kk = 0; kk < 4; kk++) {
            uint32_t ph[2][4], pl[2][4];
            #pragma unroll
            for (int i = 0; i < 2; i++) {
                uint32_t row = wm * 32 + i * 16 + r8 + ((g8 & 1) << 3);
                uint32_t colb = kk * 32 + ((g8 >> 1) << 4);
                uint32_t a = stage + row * ROW2 + colb;
                ldm_x4(ph[i], a);
                ldm_x4(pl[i], a + AV_P);
            }
            #pragma unroll
            for (int jj = 0; jj < 2; jj++) {
                uint32_t row = kk * 16 + r8 + ((g8 & 1) << 3);
                uint32_t colb = (wn * 32 + jj * 16 + ((g8 >> 1) << 3)) * 2;
                uint32_t bptr = stage + 2 * AV_P + row * ROW2 + colb;
                uint32_t bh[4], bl[4];
                ldm_x4_t(bh, bptr);
                ldm_x4_t(bl, bptr + AV_V);
                #pragma unroll
                for (int i = 0; i < 2; i++) {
                    mma_bf16(acc[i][2 * jj + 0], ph[i], bh[0], bh[1]);
                    mma_bf16(acc[i][2 * jj + 1], ph[i], bh[2], bh[3]);
                    mma_bf16(acc[i][2 * jj + 0], ph[i], bl[0], bl[1]);
                    mma_bf16(acc[i][2 * jj + 1], ph[i], bl[2], bl[3]);
                    mma_bf16(acc[i][2 * jj + 0], pl[i], bh[0], bh[1]);
                    mma_bf16(acc[i][2 * jj + 1], pl[i], bh[2], bh[3]);
                }
            }
        }
        __syncthreads();
    }

    // epilogue -> ctx bf16 hi/lo at [b*S+s, h*64+d]
    #pragma unroll
    for (int i = 0; i < 2; i++) {
        #pragma unroll
        for (int j = 0; j < 4; j++) {
            const int s0 = qb * 128 + wm * 32 + i * 16 + (lane >> 2);
            const int d0 = wn * 32 + j * 8 + (lane & 3) * 2;
            float2 lo = make_float2(acc[i][j][0], acc[i][j][1]);
            float2 hi = make_float2(acc[i][j][2], acc[i][j][3]);
            size_t off0 = (size_t)(b * S_ + s0) * D_ + h * HD_ + d0;
            split_store(g_ch + off0, g_cl + off0, lo);
            size_t off1 = (size_t)(b * S_ + s0 + 8) * D_ + h * HD_ + d0;
            split_store(g_ch + off1, g_cl + off1, hi);
        }
    }
}

// ---------------------------------------------------------------------------
extern "C" void kernel_launch(void* const* d_in, const int* in_sizes, int n_in,
                              void* d_out, int out_size)
{
    const float* x      = (const float*)d_in[0];
    const float* mask   = (const float*)d_in[1];
    const float* w_attn = (const float*)d_in[2];
    const float* b_attn = (const float*)d_in[3];
    const float* w_proj = (const float*)d_in[4];
    const float* b_proj = (const float*)d_in[5];

    float* out   = (float*)d_out;
    float* a_out = out;                         // [B,S,D]
    float* w_out = out + (size_t)M_ * D_;       // [B,H,S,S]

    __nv_bfloat16 *xh, *xl, *wah, *wal, *wph, *wpl, *ch, *cl;
    cudaGetSymbolAddress((void**)&xh,  g_xh);
    cudaGetSymbolAddress((void**)&xl,  g_xl);
    cudaGetSymbolAddress((void**)&wah, g_wah);
    cudaGetSymbolAddress((void**)&wal, g_wal);
    cudaGetSymbolAddress((void**)&wph, g_wph);
    cudaGetSymbolAddress((void**)&wpl, g_wpl);
    cudaGetSymbolAddress((void**)&ch,  g_ch);
    cudaGetSymbolAddress((void**)&cl,  g_cl);

    cudaFuncSetAttribute(gemm_mma_bf16x3,
                         cudaFuncAttributeMaxDynamicSharedMemorySize, GEMM_SMEM);
    cudaFuncSetAttribute(scores_mma,
                         cudaFuncAttributeMaxDynamicSharedMemorySize, SC_SMEM);
    cudaFuncSetAttribute(av_mma,
                         cudaFuncAttributeMaxDynamicSharedMemorySize, AV_SMEM);

    // 1) converts
    convert_rm<<<(M_ * D_ / 4 + 255) / 256, 256>>>(x, xh, xl, (size_t)M_ * D_);
    convert_transpose<<<dim3(TD_ / 32, D_ / 32), 256>>>(w_attn, wah, wal, D_, TD_);
    convert_transpose<<<dim3(D_ / 32, D_ / 32), 256>>>(w_proj, wph, wpl, D_, D_);

    // 2) QKV GEMM -> bf16 hi/lo q/k/v
    gemm_mma_bf16x3<<<dim3(TD_ / 128, M_ / 128), 128, GEMM_SMEM>>>(
        xh, xl, wah, wal, b_attn, nullptr, D_, TD_, 0);

    // 3) Scores (HMMA, lower-tri) -> softmax (emits bf16 P) -> AV (HMMA)
    scores_mma<<<dim3(36, NH_), 256, SC_SMEM>>>(w_out);
    softmax_kernel<<<NH_ * S_, 256>>>(mask, w_out);
    av_mma<<<dim3(8, NH_), 256, AV_SMEM>>>();

    // 4) Output projection
    gemm_mma_bf16x3<<<dim3(D_ / 128, M_ / 128), 128, GEMM_SMEM>>>(
        ch, cl, wph, wpl, b_proj, a_out, D_, D_, 1);
}

// round 14
// speedup vs baseline: 1.0731x; 1.0318x over previous
#include <cuda_runtime.h>
#include <cuda_bf16.h>
#include <cstdint>

#define B_  4
#define S_  1024
#define D_  1024
#define H_  16
#define HD_ 64
#define M_  (B_ * S_)        // 4096 rows
#define TD_ (3 * D_)         // 3072
#define NH_ (B_ * H_)        // 64 head-batches
#define NEG_ 10000.0f

// ---------------------------------------------------------------------------
// Scratch (allocation-free rule: __device__ globals)
// ---------------------------------------------------------------------------
__device__ __nv_bfloat16 g_qh[(size_t)NH_ * S_ * HD_];  // [head, s, 64]
__device__ __nv_bfloat16 g_ql[(size_t)NH_ * S_ * HD_];
__device__ __nv_bfloat16 g_kh[(size_t)NH_ * S_ * HD_];
__device__ __nv_bfloat16 g_kl[(size_t)NH_ * S_ * HD_];
__device__ __nv_bfloat16 g_vh[(size_t)NH_ * S_ * HD_];
__device__ __nv_bfloat16 g_vl[(size_t)NH_ * S_ * HD_];
__device__ __nv_bfloat16 g_ph[(size_t)NH_ * S_ * S_];   // unnormalized exp probs hi/lo
__device__ __nv_bfloat16 g_pl[(size_t)NH_ * S_ * S_];
__device__ __nv_bfloat16 g_ch[(size_t)M_ * D_];          // ctx hi/lo row-major
__device__ __nv_bfloat16 g_cl[(size_t)M_ * D_];
__device__ float g_inv[(size_t)NH_ * S_];                // 1/rowsum

__device__ __nv_bfloat16 g_xh[(size_t)M_ * D_];          // x hi/lo row-major
__device__ __nv_bfloat16 g_xl[(size_t)M_ * D_];
__device__ __nv_bfloat16 g_wah[(size_t)TD_ * D_];        // w_attn^T hi/lo
__device__ __nv_bfloat16 g_wal[(size_t)TD_ * D_];
__device__ __nv_bfloat16 g_wph[(size_t)D_ * D_];         // w_proj^T hi/lo
__device__ __nv_bfloat16 g_wpl[(size_t)D_ * D_];

__device__ __forceinline__ uint32_t smem_u32(const void* p) {
    uint32_t a;
    asm("{ .reg .u64 t; cvta.to.shared.u64 t, %1; cvt.u32.u64 %0, t; }" : "=r"(a) : "l"(p));
    return a;
}
__device__ __forceinline__ void cp16(uint32_t s, const void* g) {
    asm volatile("cp.async.ca.shared.global [%0], [%1], 16;" :: "r"(s), "l"(g));
}
__device__ __forceinline__ void ldm_x4(uint32_t* f, uint32_t addr) {
    asm volatile("ldmatrix.sync.aligned.m8n8.x4.shared.b16 {%0,%1,%2,%3}, [%4];"
                 : "=r"(f[0]), "=r"(f[1]), "=r"(f[2]), "=r"(f[3]) : "r"(addr));
}
__device__ __forceinline__ void ldm_x4_t(uint32_t* f, uint32_t addr) {
    asm volatile("ldmatrix.sync.aligned.m8n8.x4.trans.shared.b16 {%0,%1,%2,%3}, [%4];"
                 : "=r"(f[0]), "=r"(f[1]), "=r"(f[2]), "=r"(f[3]) : "r"(addr));
}
__device__ __forceinline__ void mma_bf16(float* d, const uint32_t* a,
                                         uint32_t b0, uint32_t b1) {
    asm volatile("mma.sync.aligned.m16n8k16.row.col.f32.bf16.bf16.f32 "
                 "{%0,%1,%2,%3}, {%4,%5,%6,%7}, {%8,%9}, {%0,%1,%2,%3};"
                 : "+f"(d[0]), "+f"(d[1]), "+f"(d[2]), "+f"(d[3])
                 : "r"(a[0]), "r"(a[1]), "r"(a[2]), "r"(a[3]), "r"(b0), "r"(b1));
}
__device__ __forceinline__ void split_store(__nv_bfloat16* ph, __nv_bfloat16* pl,
                                            float2 v) {
    __nv_bfloat16 hx = __float2bfloat16(v.x), hy = __float2bfloat16(v.y);
    *reinterpret_cast<__nv_bfloat162*>(ph) = __halves2bfloat162(hx, hy);
    *reinterpret_cast<__nv_bfloat162*>(pl) = __halves2bfloat162(
        __float2bfloat16(v.x - __bfloat162float(hx)),
        __float2bfloat16(v.y - __bfloat162float(hy)));
}

// ---------------------------------------------------------------------------
// Conversion kernels
// ---------------------------------------------------------------------------
__global__ __launch_bounds__(256) void convert_rm(
    const float* __restrict__ in, __nv_bfloat16* __restrict__ oh,
    __nv_bfloat16* __restrict__ ol, size_t n)
{
    size_t i = ((size_t)blockIdx.x * 256 + threadIdx.x) * 4;
    if (i >= n) return;
    float4 v = *reinterpret_cast<const float4*>(in + i);
    split_store(oh + i, ol + i, make_float2(v.x, v.y));
    split_store(oh + i + 2, ol + i + 2, make_float2(v.z, v.w));
}

__global__ __launch_bounds__(256) void convert_transpose(
    const float* __restrict__ in, __nv_bfloat16* __restrict__ oh,
    __nv_bfloat16* __restrict__ ol, int R, int C)
{
    __shared__ float t[32][33];
    const int c0 = blockIdx.x * 32, r0 = blockIdx.y * 32;
    const int tx = threadIdx.x & 31, ty = threadIdx.x >> 5;
    #pragma unroll
    for (int i = 0; i < 32; i += 8)
        t[ty + i][tx] = in[(size_t)(r0 + ty + i) * C + c0 + tx];
    __syncthreads();
    #pragma unroll
    for (int i = 0; i < 32; i += 8) {
        float v = t[tx][ty + i];
        __nv_bfloat16 h = __float2bfloat16(v);
        oh[(size_t)(c0 + ty + i) * R + r0 + tx] = h;
        ol[(size_t)(c0 + ty + i) * R + r0 + tx] =
            __float2bfloat16(v - __bfloat162float(h));
    }
}

// ---------------------------------------------------------------------------
// mma.sync bf16x3 GEMM, CTA 128x128, 4 warps of 64x64, K-chunk 32,
// cp.async x2. (128,2). Bench-verified 223.6us on QKV.
// mode 0: QKV epilogue -> bf16 hi/lo q/k/v; mode 1: fp32+bias -> Cout.
// ---------------------------------------------------------------------------
#define ROWB 80
#define TILEB (128 * ROWB)
#define STG_BYTES (4 * TILEB)
#define GEMM_SMEM (2 * STG_BYTES)

__global__ __launch_bounds__(128, 2) void gemm_mma_bf16x3(
    const __nv_bfloat16* __restrict__ Ah, const __nv_bfloat16* __restrict__ Al,
    const __nv_bfloat16* __restrict__ Bh, const __nv_bfloat16* __restrict__ Bl,
    const float* __restrict__ bias, float* __restrict__ Cout,
    int Kdim, int Ncols, int mode)
{
    extern __shared__ char smem[];
    const uint32_t sb = smem_u32(smem);
    const int tid = threadIdx.x;
    const int lane = tid & 31;
    const int wid = tid >> 5;
    const int wm = wid & 1;
    const int wn = wid >> 1;
    const int block_row = blockIdx.y * 128;
    const int block_col = blockIdx.x * 128;

    const __nv_bfloat16* srcs[4] = {
        Ah + (size_t)block_row * Kdim, Al + (size_t)block_row * Kdim,
        Bh + (size_t)block_col * Kdim, Bl + (size_t)block_col * Kdim};

    float acc[4][8][4];
    #pragma unroll
    for (int i = 0; i < 4; i++)
        #pragma unroll
        for (int j = 0; j < 8; j++)
            #pragma unroll
            for (int q = 0; q < 4; q++) acc[i][j][q] = 0.0f;

    const int nch = Kdim / 32;

    auto issue = [&](int c) {
        const int k0 = c * 32;
        const uint32_t stage = sb + (uint32_t)(c & 1) * STG_BYTES;
        #pragma unroll
        for (int t = 0; t < 16; t++) {
            int idx = tid + t * 128;
            int tile = idx >> 9;
            int r = (idx >> 2) & 127;
            int ch = idx & 3;
            const __nv_bfloat16* g = srcs[tile] + (size_t)r * Kdim + k0 + ch * 8;
            cp16(stage + (uint32_t)tile * TILEB + (uint32_t)r * ROWB + ch * 16, g);
        }
        asm volatile("cp.async.commit_group;");
    };

    issue(0);

    const int g8 = lane >> 3;
    const int r8 = lane & 7;

    for (int c = 0; c < nch; c++) {
        asm volatile("cp.async.wait_group 0;");
        __syncthreads();
        if (c + 1 < nch) issue(c + 1);
        const uint32_t stage = sb + (uint32_t)(c & 1) * STG_BYTES;

        #pragma unroll
        for (int kk = 0; kk < 2; kk++) {
            uint32_t ah[4][4], al[4][4];
            #pragma unroll
            for (int i = 0; i < 4; i++) {
                uint32_t row = wm * 64 + i * 16 + r8 + ((g8 & 1) << 3);
                uint32_t colb = kk * 32 + ((g8 >> 1) << 4);
                uint32_t a = stage + row * ROWB + colb;
                ldm_x4(ah[i], a);
                ldm_x4(al[i], a + TILEB);
            }
            #pragma unroll
            for (int jj = 0; jj < 4; jj++) {
                uint32_t nrow = wn * 64 + jj * 16 + r8 + ((g8 >> 1) << 3);
                uint32_t colb = kk * 32 + ((g8 & 1) << 4);
                uint32_t bptr = stage + 2 * TILEB + nrow * ROWB + colb;
                uint32_t bh[4], bl[4];
                ldm_x4(bh, bptr);
                ldm_x4(bl, bptr + TILEB);
                #pragma unroll
                for (int i = 0; i < 4; i++) {
                    mma_bf16(acc[i][2 * jj + 0], ah[i], bh[0], bh[1]);
                    mma_bf16(acc[i][2 * jj + 1], ah[i], bh[2], bh[3]);
                    mma_bf16(acc[i][2 * jj + 0], ah[i], bl[0], bl[1]);
                    mma_bf16(acc[i][2 * jj + 1], ah[i], bl[2], bl[3]);
                    mma_bf16(acc[i][2 * jj + 0], al[i], bh[0], bh[1]);
                    mma_bf16(acc[i][2 * jj + 1], al[i], bh[2], bh[3]);
                }
            }
        }
        __syncthreads();
    }

    #pragma unroll
    for (int i = 0; i < 4; i++) {
        #pragma unroll
        for (int j = 0; j < 8; j++) {
            const int r0 = block_row + wm * 64 + i * 16 + (lane >> 2);
            const int n0 = block_col + wn * 64 + j * 8 + (lane & 3) * 2;
            const float bx = bias[n0], by = bias[n0 + 1];
            float2 lo = make_float2(acc[i][j][0] + bx, acc[i][j][1] + by);
            float2 hi = make_float2(acc[i][j][2] + bx, acc[i][j][3] + by);
            if (mode == 1) {
                *reinterpret_cast<float2*>(Cout + (size_t)r0 * Ncols + n0) = lo;
                *reinterpret_cast<float2*>(Cout + (size_t)(r0 + 8) * Ncols + n0) = hi;
            } else {
                const int part = n0 >> 10;
                const int within = n0 & (D_ - 1);
                const int h = within >> 6;
                const int hd = within & 63;
                __nv_bfloat16* bh_ = (part == 0 ? g_qh : part == 1 ? g_kh : g_vh);
                __nv_bfloat16* bl_ = (part == 0 ? g_ql : part == 1 ? g_kl : g_vl);
                const int b0r = r0 >> 10, s0 = r0 & (S_ - 1);
                size_t off0 = ((size_t)((b0r << 4) + h) * S_ + s0) * HD_ + hd;
                split_store(bh_ + off0, bl_ + off0, lo);
                const int r1 = r0 + 8;
                const int b1r = r1 >> 10, s1 = r1 & (S_ - 1);
                size_t off1 = ((size_t)((b1r << 4) + h) * S_ + s1) * HD_ + hd;
                split_store(bh_ + off1, bl_ + off1, hi);
            }
        }
    }
}

// ---------------------------------------------------------------------------
// Scores via HMMA bf16x3 + fused exp (no-max, clamp 80; validated R6):
// writes UNNORMALIZED exp probs as bf16 hi/lo to g_ph/g_pl (lower tiles only,
// diag zeroed above qi). No fp32 score write.
// ---------------------------------------------------------------------------
#define ROW2 144
#define STILE (128 * ROW2)     // 18432
#define SC_SMEM (4 * STILE)    // 73728

__global__ __launch_bounds__(256, 2) void scores_mma(const float* __restrict__ mask)
{
    extern __shared__ char smem[];
    const uint32_t sb = smem_u32(smem);
    const int head = blockIdx.y;
    int t = blockIdx.x, qb = 0;
    while (t >= qb + 1) { t -= qb + 1; qb++; }
    const int kb = t;
    const int b = head >> 4;

    const int tid = threadIdx.x;
    const int lane = tid & 31;
    const int wid = tid >> 5;
    const int wm = wid & 3;
    const int wn = wid >> 2;
    const int g8 = lane >> 3;
    const int r8 = lane & 7;

    const __nv_bfloat16* srcs[4] = {
        g_qh + ((size_t)head * S_ + qb * 128) * HD_,
        g_ql + ((size_t)head * S_ + qb * 128) * HD_,
        g_kh + ((size_t)head * S_ + kb * 128) * HD_,
        g_kl + ((size_t)head * S_ + kb * 128) * HD_};

    #pragma unroll
    for (int tt = 0; tt < 16; tt++) {
        int idx = tid + tt * 256;
        int tile = idx >> 10;
        int r = (idx >> 3) & 127;
        int ch = idx & 7;
        cp16(sb + (uint32_t)tile * STILE + (uint32_t)r * ROW2 + ch * 16,
             srcs[tile] + (size_t)r * HD_ + ch * 8);
    }
    asm volatile("cp.async.commit_group;");
    asm volatile("cp.async.wait_group 0;");
    __syncthreads();

    float acc[2][8][4];
    #pragma unroll
    for (int i = 0; i < 2; i++)
        #pragma unroll
        for (int j = 0; j < 8; j++)
            #pragma unroll
            for (int q = 0; q < 4; q++) acc[i][j][q] = 0.0f;

    #pragma unroll
    for (int kk = 0; kk < 4; kk++) {
        uint32_t ah[2][4], al[2][4];
        #pragma unroll
        for (int i = 0; i < 2; i++) {
            uint32_t row = wm * 32 + i * 16 + r8 + ((g8 & 1) << 3);
            uint32_t colb = kk * 32 + ((g8 >> 1) << 4);
            uint32_t a = sb + row * ROW2 + colb;
            ldm_x4(ah[i], a);
            ldm_x4(al[i], a + STILE);
        }
        #pragma unroll
        for (int jj = 0; jj < 4; jj++) {
            uint32_t nrow = wn * 64 + jj * 16 + r8 + ((g8 >> 1) << 3);
            uint32_t colb = kk * 32 + ((g8 & 1) << 4);
            uint32_t bptr = sb + 2 * STILE + nrow * ROW2 + colb;
            uint32_t bh[4], bl[4];
            ldm_x4(bh, bptr);
            ldm_x4(bl, bptr + STILE);
            #pragma unroll
            for (int i = 0; i < 2; i++) {
                mma_bf16(acc[i][2 * jj + 0], ah[i], bh[0], bh[1]);
                mma_bf16(acc[i][2 * jj + 1], ah[i], bh[2], bh[3]);
                mma_bf16(acc[i][2 * jj + 0], ah[i], bl[0], bl[1]);
                mma_bf16(acc[i][2 * jj + 1], ah[i], bl[2], bl[3]);
                mma_bf16(acc[i][2 * jj + 0], al[i], bh[0], bh[1]);
                mma_bf16(acc[i][2 * jj + 1], al[i], bh[2], bh[3]);
            }
        }
    }

    const bool diag = (qb == kb);
    const float* mrow = mask + b * S_;
    #pragma unroll
    for (int i = 0; i < 2; i++) {
        #pragma unroll
        for (int j = 0; j < 8; j++) {
            const int qi0 = qb * 128 + wm * 32 + i * 16 + (lane >> 2);
            const int kj = kb * 128 + wn * 64 + j * 8 + (lane & 3) * 2;
            float2 mv = *reinterpret_cast<const float2*>(mrow + kj);
            float s0 = fminf(acc[i][j][0] * 0.125f + mv.x, 80.0f);
            float s1 = fminf(acc[i][j][1] * 0.125f + mv.y, 80.0f);
            float s2 = fminf(acc[i][j][2] * 0.125f + mv.x, 80.0f);
            float s3 = fminf(acc[i][j][3] * 0.125f + mv.y, 80.0f);
            float e0 = __expf(s0), e1 = __expf(s1);
            float e2 = __expf(s2), e3 = __expf(s3);
            if (diag) {
                if (kj + 0 > qi0) e0 = 0.0f;
                if (kj + 1 > qi0) e1 = 0.0f;
                if (kj + 0 > qi0 + 8) e2 = 0.0f;
                if (kj + 1 > qi0 + 8) e3 = 0.0f;
            }
            size_t off = ((size_t)head * S_ + qi0) * S_ + kj;
            split_store(g_ph + off, g_pl + off, make_float2(e0, e1));
            split_store(g_ph + off + 8 * S_, g_pl + off + 8 * S_,
                        make_float2(e2, e3));
        }
    }
}

// ---------------------------------------------------------------------------
// AV via HMMA bf16x3 on UNNORMALIZED probs; rowsums via P x ones MMA
// (wn==0 warps); epilogue: inv = 1/sum via smem exchange, scale ctx,
// write g_inv for the normalize kernel.
// ---------------------------------------------------------------------------
#define AV_P  18432              // P tile bytes (128 x 144)
#define AV_V  9216               // V tile bytes (64 x 144)
#define AV_STG (2 * AV_P + 2 * AV_V)   // 55296
#define AV_SMEM (2 * AV_STG)           // 110592
#define ONES_BF16X2 0x3F803F80u

__global__ __launch_bounds__(256, 2) void av_mma()
{
    extern __shared__ char smem[];
    const uint32_t sb = smem_u32(smem);
    const int head = blockIdx.y;
    const int qb = 7 - blockIdx.x;     // big tiles first
    const int b = head >> 4;
    const int h = head & 15;

    const int tid = threadIdx.x;
    const int lane = tid & 31;
    const int wid = tid >> 5;
    const int wm = wid & 3;
    const int wn = wid >> 2;
    const int g8 = lane >> 3;
    const int r8 = lane & 7;

    const __nv_bfloat16* Phb = g_ph + ((size_t)head * S_ + qb * 128) * S_;
    const __nv_bfloat16* Plb = g_pl + ((size_t)head * S_ + qb * 128) * S_;
    const __nv_bfloat16* Vhb = g_vh + (size_t)head * S_ * HD_;
    const __nv_bfloat16* Vlb = g_vl + (size_t)head * S_ * HD_;

    const int nch = 2 * (qb + 1);      // K-chunks of 64

    auto issue = [&](int c) {
        const int k0 = c * 64;
        const uint32_t stage = sb + (uint32_t)(c & 1) * AV_STG;
        #pragma unroll
        for (int t = 0; t < 12; t++) {
            int idx = tid + t * 256;
            if (idx < 2048) {
                int tile = idx >> 10;              // 0 Ph, 1 Pl
                int r = (idx >> 3) & 127;
                int ch = idx & 7;
                const __nv_bfloat16* g = (tile ? Plb : Phb) + (size_t)r * S_ + k0 + ch * 8;
                cp16(stage + (uint32_t)tile * AV_P + (uint32_t)r * ROW2 + ch * 16, g);
            } else {
                int v = idx - 2048;
                int tile = v >> 9;                 // 0 Vh, 1 Vl
                int r = (v >> 3) & 63;
                int ch = v & 7;
                const __nv_bfloat16* g = (tile ? Vlb : Vhb) + (size_t)(k0 + r) * HD_ + ch * 8;
                cp16(stage + 2 * AV_P + (uint32_t)tile * AV_V + (uint32_t)r * ROW2 + ch * 16, g);
            }
        }
        asm volatile("cp.async.commit_group;");
    };

    float acc[2][4][4];
    #pragma unroll
    for (int i = 0; i < 2; i++)
        #pragma unroll
        for (int j = 0; j < 4; j++)
            #pragma unroll
            for (int q = 0; q < 4; q++) acc[i][j][q] = 0.0f;
    float accS[2][4];
    #pragma unroll
    for (int i = 0; i < 2; i++)
        #pragma unroll
        for (int q = 0; q < 4; q++) accS[i][q] = 0.0f;

    issue(0);
    for (int c = 0; c < nch; c++) {
        if (c + 1 < nch) {
            issue(c + 1);
            asm volatile("cp.async.wait_group 1;");
        } else {
            asm volatile("cp.async.wait_group 0;");
        }
        __syncthreads();
        const uint32_t stage = sb + (uint32_t)(c & 1) * AV_STG;

        #pragma unroll
        for (int kk = 0; kk < 4; kk++) {
            uint32_t ph[2][4], pl[2][4];
            #pragma unroll
            for (int i = 0; i < 2; i++) {
                uint32_t row = wm * 32 + i * 16 + r8 + ((g8 & 1) << 3);
                uint32_t colb = kk * 32 + ((g8 >> 1) << 4);
                uint32_t a = stage + row * ROW2 + colb;
                ldm_x4(ph[i], a);
                ldm_x4(pl[i], a + AV_P);
            }
            if (wn == 0) {       // rowsum accumulators via P x ones
                mma_bf16(accS[0], ph[0], ONES_BF16X2, ONES_BF16X2);
                mma_bf16(accS[1], ph[1], ONES_BF16X2, ONES_BF16X2);
                mma_bf16(accS[0], pl[0], ONES_BF16X2, ONES_BF16X2);
                mma_bf16(accS[1], pl[1], ONES_BF16X2, ONES_BF16X2);
            }
            #pragma unroll
            for (int jj = 0; jj < 2; jj++) {
                uint32_t row = kk * 16 + r8 + ((g8 & 1) << 3);
                uint32_t colb = (wn * 32 + jj * 16 + ((g8 >> 1) << 3)) * 2;
                uint32_t bptr = stage + 2 * AV_P + row * ROW2 + colb;
                uint32_t bh[4], bl[4];
                ldm_x4_t(bh, bptr);
                ldm_x4_t(bl, bptr + AV_V);
                #pragma unroll
                for (int i = 0; i < 2; i++) {
                    mma_bf16(acc[i][2 * jj + 0], ph[i], bh[0], bh[1]);
                    mma_bf16(acc[i][2 * jj + 1], ph[i], bh[2], bh[3]);
                    mma_bf16(acc[i][2 * jj + 0], ph[i], bl[0], bl[1]);
                    mma_bf16(acc[i][2 * jj + 1], ph[i], bl[2], bl[3]);
                    mma_bf16(acc[i][2 * jj + 0], pl[i], bh[0], bh[1]);
                    mma_bf16(acc[i][2 * jj + 1], pl[i], bh[2], bh[3]);
                }
            }
        }
        __syncthreads();
    }

    // inv exchange: wn==0 holds rowsums (all 4 lanes of a quad identical)
    float* invbuf = reinterpret_cast<float*>(smem);
    if (wn == 0 && (lane & 3) == 0) {
        #pragma unroll
        for (int i = 0; i < 2; i++) {
            const int rl = wm * 32 + i * 16 + (lane >> 2);
            float iv0 = 1.0f / accS[i][0];
            float iv1 = 1.0f / accS[i][2];
            invbuf[rl] = iv0;
            invbuf[rl + 8] = iv1;
            g_inv[(size_t)head * S_ + qb * 128 + rl] = iv0;
            g_inv[(size_t)head * S_ + qb * 128 + rl + 8] = iv1;
        }
    }
    __syncthreads();

    // epilogue -> ctx bf16 hi/lo at [b*S+s, h*64+d], scaled by inv
    #pragma unroll
    for (int i = 0; i < 2; i++) {
        const int rl = wm * 32 + i * 16 + (lane >> 2);
        const float iv0 = invbuf[rl];
        const float iv1 = invbuf[rl + 8];
        #pragma unroll
        for (int j = 0; j < 4; j++) {
            const int s0 = qb * 128 + rl;
            const int d0 = wn * 32 + j * 8 + (lane & 3) * 2;
            float2 lo = make_float2(acc[i][j][0] * iv0, acc[i][j][1] * iv0);
            float2 hi = make_float2(acc[i][j][2] * iv1, acc[i][j][3] * iv1);
            size_t off0 = (size_t)(b * S_ + s0) * D_ + h * HD_ + d0;
            split_store(g_ch + off0, g_cl + off0, lo);
            size_t off1 = (size_t)(b * S_ + s0 + 8) * D_ + h * HD_ + d0;
            split_store(g_ch + off1, g_cl + off1, hi);
        }
    }
}

// ---------------------------------------------------------------------------
// Normalize: w[head,qi,j] = (ph+pl)*inv for j<valid, 0 beyond. DRAM-bound;
// runs on a second stream concurrently with the proj GEMM.
// ---------------------------------------------------------------------------
__global__ __launch_bounds__(256) void normalize_w(float* __restrict__ w_out)
{
    const int idx = blockIdx.x;          // head*S + qi
    const int qi = idx & (S_ - 1);
    const int valid = ((qi >> 7) + 1) << 7;
    const float inv = g_inv[idx];
    const int j0 = threadIdx.x * 4;

    float4 o;
    if (j0 < valid) {
        size_t off = (size_t)idx * S_ + j0;
        __nv_bfloat162 h0 = *reinterpret_cast<const __nv_bfloat162*>(g_ph + off);
        __nv_bfloat162 h1 = *reinterpret_cast<const __nv_bfloat162*>(g_ph + off + 2);
        __nv_bfloat162 l0 = *reinterpret_cast<const __nv_bfloat162*>(g_pl + off);
        __nv_bfloat162 l1 = *reinterpret_cast<const __nv_bfloat162*>(g_pl + off + 2);
        o.x = (__bfloat162float(h0.x) + __bfloat162float(l0.x)) * inv;
        o.y = (__bfloat162float(h0.y) + __bfloat162float(l0.y)) * inv;
        o.z = (__bfloat162float(h1.x) + __bfloat162float(l1.x)) * inv;
        o.w = (__bfloat162float(h1.y) + __bfloat162float(l1.y)) * inv;
    } else {
        o = make_float4(0.f, 0.f, 0.f, 0.f);
    }
    *reinterpret_cast<float4*>(w_out + (size_t)idx * S_ + j0) = o;
}

// ---------------------------------------------------------------------------
extern "C" void kernel_launch(void* const* d_in, const int* in_sizes, int n_in,
                              void* d_out, int out_size)
{
    const float* x      = (const float*)d_in[0];
    const float* mask   = (const float*)d_in[1];
    const float* w_attn = (const float*)d_in[2];
    const float* b_attn = (const float*)d_in[3];
    const float* w_proj = (const float*)d_in[4];
    const float* b_proj = (const float*)d_in[5];

    float* out   = (float*)d_out;
    float* a_out = out;                         // [B,S,D]
    float* w_out = out + (size_t)M_ * D_;       // [B,H,S,S]

    __nv_bfloat16 *xh, *xl, *wah, *wal, *wph, *wpl, *ch, *cl;
    cudaGetSymbolAddress((void**)&xh,  g_xh);
    cudaGetSymbolAddress((void**)&xl,  g_xl);
    cudaGetSymbolAddress((void**)&wah, g_wah);
    cudaGetSymbolAddress((void**)&wal, g_wal);
    cudaGetSymbolAddress((void**)&wph, g_wph);
    cudaGetSymbolAddress((void**)&wpl, g_wpl);
    cudaGetSymbolAddress((void**)&ch,  g_ch);
    cudaGetSymbolAddress((void**)&cl,  g_cl);

    static cudaStream_t s2 = nullptr;
    static cudaEvent_t ev1 = nullptr, ev2 = nullptr;
    if (!s2) {
        cudaStreamCreateWithFlags(&s2, cudaStreamNonBlocking);
        cudaEventCreateWithFlags(&ev1, cudaEventDisableTiming);
        cudaEventCreateWithFlags(&ev2, cudaEventDisableTiming);
    }

    cudaFuncSetAttribute(gemm_mma_bf16x3,
                         cudaFuncAttributeMaxDynamicSharedMemorySize, GEMM_SMEM);
    cudaFuncSetAttribute(scores_mma,
                         cudaFuncAttributeMaxDynamicSharedMemorySize, SC_SMEM);
    cudaFuncSetAttribute(av_mma,
                         cudaFuncAttributeMaxDynamicSharedMemorySize, AV_SMEM);

    // 1) converts
    convert_rm<<<(M_ * D_ / 4 + 255) / 256, 256>>>(x, xh, xl, (size_t)M_ * D_);
    convert_transpose<<<dim3(TD_ / 32, D_ / 32), 256>>>(w_attn, wah, wal, D_, TD_);
    convert_transpose<<<dim3(D_ / 32, D_ / 32), 256>>>(w_proj, wph, wpl, D_, D_);

    // 2) QKV GEMM -> bf16 hi/lo q/k/v
    gemm_mma_bf16x3<<<dim3(TD_ / 128, M_ / 128), 128, GEMM_SMEM>>>(
        xh, xl, wah, wal, b_attn, nullptr, D_, TD_, 0);

    // 3) Scores+exp (unnormalized probs) -> AV (rowsums + inv + ctx)
    scores_mma<<<dim3(36, NH_), 256, SC_SMEM>>>(mask);
    av_mma<<<dim3(8, NH_), 256, AV_SMEM>>>();

    // 4) Fork: normalize w on s2  ||  proj GEMM on main stream
    cudaEventRecord(ev1, 0);
    cudaStreamWaitEvent(s2, ev1, 0);
    normalize_w<<<NH_ * S_, 256, 0, s2>>>(w_out);
    cudaEventRecord(ev2, s2);

    gemm_mma_bf16x3<<<dim3(D_ / 128, M_ / 128), 128, GEMM_SMEM>>>(
        ch, cl, wph, wpl, b_proj, a_out, D_, D_, 1);

    cudaStreamWaitEvent(0, ev2, 0);
}

// round 16
// speedup vs baseline: 1.1581x; 1.0793x over previous
#include <cuda_runtime.h>
#include <cuda_bf16.h>
#include <cstdint>

#define B_  4
#define S_  1024
#define D_  1024
#define H_  16
#define HD_ 64
#define M_  (B_ * S_)        // 4096 rows
#define TD_ (3 * D_)         // 3072
#define NH_ (B_ * H_)        // 64 head-batches
#define NEG_ 10000.0f

// ---------------------------------------------------------------------------
// Scratch (allocation-free rule: __device__ globals)
// ---------------------------------------------------------------------------
__device__ __nv_bfloat16 g_qh[(size_t)NH_ * S_ * HD_];  // [head, s, 64]
__device__ __nv_bfloat16 g_ql[(size_t)NH_ * S_ * HD_];
__device__ __nv_bfloat16 g_kh[(size_t)NH_ * S_ * HD_];
__device__ __nv_bfloat16 g_kl[(size_t)NH_ * S_ * HD_];
__device__ __nv_bfloat16 g_vh[(size_t)NH_ * S_ * HD_];
__device__ __nv_bfloat16 g_vl[(size_t)NH_ * S_ * HD_];
__device__ __nv_bfloat16 g_ph[(size_t)NH_ * S_ * S_];   // unnormalized exp probs hi/lo
__device__ __nv_bfloat16 g_pl[(size_t)NH_ * S_ * S_];
__device__ __nv_bfloat16 g_ch[(size_t)M_ * D_];          // ctx hi/lo row-major
__device__ __nv_bfloat16 g_cl[(size_t)M_ * D_];
__device__ float g_inv[(size_t)NH_ * S_];                // 1/rowsum

__device__ __nv_bfloat16 g_xh[(size_t)M_ * D_];          // x hi/lo row-major
__device__ __nv_bfloat16 g_xl[(size_t)M_ * D_];
__device__ __nv_bfloat16 g_wah[(size_t)TD_ * D_];        // w_attn^T hi/lo
__device__ __nv_bfloat16 g_wal[(size_t)TD_ * D_];
__device__ __nv_bfloat16 g_wph[(size_t)D_ * D_];         // w_proj^T hi/lo
__device__ __nv_bfloat16 g_wpl[(size_t)D_ * D_];

__device__ __forceinline__ uint32_t smem_u32(const void* p) {
    uint32_t a;
    asm("{ .reg .u64 t; cvta.to.shared.u64 t, %1; cvt.u32.u64 %0, t; }" : "=r"(a) : "l"(p));
    return a;
}
__device__ __forceinline__ void cp16(uint32_t s, const void* g) {
    asm volatile("cp.async.ca.shared.global [%0], [%1], 16;" :: "r"(s), "l"(g));
}
__device__ __forceinline__ void ldm_x4(uint32_t* f, uint32_t addr) {
    asm volatile("ldmatrix.sync.aligned.m8n8.x4.shared.b16 {%0,%1,%2,%3}, [%4];"
                 : "=r"(f[0]), "=r"(f[1]), "=r"(f[2]), "=r"(f[3]) : "r"(addr));
}
__device__ __forceinline__ void ldm_x4_t(uint32_t* f, uint32_t addr) {
    asm volatile("ldmatrix.sync.aligned.m8n8.x4.trans.shared.b16 {%0,%1,%2,%3}, [%4];"
                 : "=r"(f[0]), "=r"(f[1]), "=r"(f[2]), "=r"(f[3]) : "r"(addr));
}
__device__ __forceinline__ void mma_bf16(float* d, const uint32_t* a,
                                         uint32_t b0, uint32_t b1) {
    asm volatile("mma.sync.aligned.m16n8k16.row.col.f32.bf16.bf16.f32 "
                 "{%0,%1,%2,%3}, {%4,%5,%6,%7}, {%8,%9}, {%0,%1,%2,%3};"
                 : "+f"(d[0]), "+f"(d[1]), "+f"(d[2]), "+f"(d[3])
                 : "r"(a[0]), "r"(a[1]), "r"(a[2]), "r"(a[3]), "r"(b0), "r"(b1));
}
__device__ __forceinline__ void split_store(__nv_bfloat16* ph, __nv_bfloat16* pl,
                                            float2 v) {
    __nv_bfloat16 hx = __float2bfloat16(v.x), hy = __float2bfloat16(v.y);
    *reinterpret_cast<__nv_bfloat162*>(ph) = __halves2bfloat162(hx, hy);
    *reinterpret_cast<__nv_bfloat162*>(pl) = __halves2bfloat162(
        __float2bfloat16(v.x - __bfloat162float(hx)),
        __float2bfloat16(v.y - __bfloat162float(hy)));
}

// ---------------------------------------------------------------------------
// Conversion kernels
// ---------------------------------------------------------------------------
__global__ __launch_bounds__(256) void convert_rm(
    const float* __restrict__ in, __nv_bfloat16* __restrict__ oh,
    __nv_bfloat16* __restrict__ ol, size_t n)
{
    size_t i = ((size_t)blockIdx.x * 256 + threadIdx.x) * 4;
    if (i >= n) return;
    float4 v = *reinterpret_cast<const float4*>(in + i);
    split_store(oh + i, ol + i, make_float2(v.x, v.y));
    split_store(oh + i + 2, ol + i + 2, make_float2(v.z, v.w));
}

__global__ __launch_bounds__(256) void convert_transpose(
    const float* __restrict__ in, __nv_bfloat16* __restrict__ oh,
    __nv_bfloat16* __restrict__ ol, int R, int C)
{
    __shared__ float t[32][33];
    const int c0 = blockIdx.x * 32, r0 = blockIdx.y * 32;
    const int tx = threadIdx.x & 31, ty = threadIdx.x >> 5;
    #pragma unroll
    for (int i = 0; i < 32; i += 8)
        t[ty + i][tx] = in[(size_t)(r0 + ty + i) * C + c0 + tx];
    __syncthreads();
    #pragma unroll
    for (int i = 0; i < 32; i += 8) {
        float v = t[tx][ty + i];
        __nv_bfloat16 h = __float2bfloat16(v);
        oh[(size_t)(c0 + ty + i) * R + r0 + tx] = h;
        ol[(size_t)(c0 + ty + i) * R + r0 + tx] =
            __float2bfloat16(v - __bfloat162float(h));
    }
}

// ---------------------------------------------------------------------------
// mma.sync bf16x3 GEMM, CTA 128x128, 4 warps of 64x64, K-chunk 32,
// cp.async x2. (128,2). col0: column offset (QK/V split).
// mode 0: QKV epilogue -> bf16 hi/lo q/k/v; mode 1: fp32+bias -> Cout.
// ---------------------------------------------------------------------------
#define ROWB 80
#define TILEB (128 * ROWB)
#define STG_BYTES (4 * TILEB)
#define GEMM_SMEM (2 * STG_BYTES)

__global__ __launch_bounds__(128, 2) void gemm_mma_bf16x3(
    const __nv_bfloat16* __restrict__ Ah, const __nv_bfloat16* __restrict__ Al,
    const __nv_bfloat16* __restrict__ Bh, const __nv_bfloat16* __restrict__ Bl,
    const float* __restrict__ bias, float* __restrict__ Cout,
    int Kdim, int Ncols, int mode, int col0)
{
    extern __shared__ char smem[];
    const uint32_t sb = smem_u32(smem);
    const int tid = threadIdx.x;
    const int lane = tid & 31;
    const int wid = tid >> 5;
    const int wm = wid & 1;
    const int wn = wid >> 1;
    const int block_row = blockIdx.y * 128;
    const int block_col = col0 + blockIdx.x * 128;

    const __nv_bfloat16* srcs[4] = {
        Ah + (size_t)block_row * Kdim, Al + (size_t)block_row * Kdim,
        Bh + (size_t)block_col * Kdim, Bl + (size_t)block_col * Kdim};

    float acc[4][8][4];
    #pragma unroll
    for (int i = 0; i < 4; i++)
        #pragma unroll
        for (int j = 0; j < 8; j++)
            #pragma unroll
            for (int q = 0; q < 4; q++) acc[i][j][q] = 0.0f;

    const int nch = Kdim / 32;

    auto issue = [&](int c) {
        const int k0 = c * 32;
        const uint32_t stage = sb + (uint32_t)(c & 1) * STG_BYTES;
        #pragma unroll
        for (int t = 0; t < 16; t++) {
            int idx = tid + t * 128;
            int tile = idx >> 9;
            int r = (idx >> 2) & 127;
            int ch = idx & 3;
            const __nv_bfloat16* g = srcs[tile] + (size_t)r * Kdim + k0 + ch * 8;
            cp16(stage + (uint32_t)tile * TILEB + (uint32_t)r * ROWB + ch * 16, g);
        }
        asm volatile("cp.async.commit_group;");
    };

    issue(0);

    const int g8 = lane >> 3;
    const int r8 = lane & 7;

    for (int c = 0; c < nch; c++) {
        asm volatile("cp.async.wait_group 0;");
        __syncthreads();
        if (c + 1 < nch) issue(c + 1);
        const uint32_t stage = sb + (uint32_t)(c & 1) * STG_BYTES;

        #pragma unroll
        for (int kk = 0; kk < 2; kk++) {
            uint32_t ah[4][4], al[4][4];
            #pragma unroll
            for (int i = 0; i < 4; i++) {
                uint32_t row = wm * 64 + i * 16 + r8 + ((g8 & 1) << 3);
                uint32_t colb = kk * 32 + ((g8 >> 1) << 4);
                uint32_t a = stage + row * ROWB + colb;
                ldm_x4(ah[i], a);
                ldm_x4(al[i], a + TILEB);
            }
            #pragma unroll
            for (int jj = 0; jj < 4; jj++) {
                uint32_t nrow = wn * 64 + jj * 16 + r8 + ((g8 >> 1) << 3);
                uint32_t colb = kk * 32 + ((g8 & 1) << 4);
                uint32_t bptr = stage + 2 * TILEB + nrow * ROWB + colb;
                uint32_t bh[4], bl[4];
                ldm_x4(bh, bptr);
                ldm_x4(bl, bptr + TILEB);
                #pragma unroll
                for (int i = 0; i < 4; i++) {
                    mma_bf16(acc[i][2 * jj + 0], ah[i], bh[0], bh[1]);
                    mma_bf16(acc[i][2 * jj + 1], ah[i], bh[2], bh[3]);
                    mma_bf16(acc[i][2 * jj + 0], ah[i], bl[0], bl[1]);
                    mma_bf16(acc[i][2 * jj + 1], ah[i], bl[2], bl[3]);
                    mma_bf16(acc[i][2 * jj + 0], al[i], bh[0], bh[1]);
                    mma_bf16(acc[i][2 * jj + 1], al[i], bh[2], bh[3]);
                }
            }
        }
        __syncthreads();
    }

    #pragma unroll
    for (int i = 0; i < 4; i++) {
        #pragma unroll
        for (int j = 0; j < 8; j++) {
            const int r0 = block_row + wm * 64 + i * 16 + (lane >> 2);
            const int n0 = block_col + wn * 64 + j * 8 + (lane & 3) * 2;
            const float bx = bias[n0], by = bias[n0 + 1];
            float2 lo = make_float2(acc[i][j][0] + bx, acc[i][j][1] + by);
            float2 hi = make_float2(acc[i][j][2] + bx, acc[i][j][3] + by);
            if (mode == 1) {
                *reinterpret_cast<float2*>(Cout + (size_t)r0 * Ncols + n0) = lo;
                *reinterpret_cast<float2*>(Cout + (size_t)(r0 + 8) * Ncols + n0) = hi;
            } else {
                const int part = n0 >> 10;
                const int within = n0 & (D_ - 1);
                const int h = within >> 6;
                const int hd = within & 63;
                __nv_bfloat16* bh_ = (part == 0 ? g_qh : part == 1 ? g_kh : g_vh);
                __nv_bfloat16* bl_ = (part == 0 ? g_ql : part == 1 ? g_kl : g_vl);
                const int b0r = r0 >> 10, s0 = r0 & (S_ - 1);
                size_t off0 = ((size_t)((b0r << 4) + h) * S_ + s0) * HD_ + hd;
                split_store(bh_ + off0, bl_ + off0, lo);
                const int r1 = r0 + 8;
                const int b1r = r1 >> 10, s1 = r1 & (S_ - 1);
                size_t off1 = ((size_t)((b1r << 4) + h) * S_ + s1) * HD_ + hd;
                split_store(bh_ + off1, bl_ + off1, hi);
            }
        }
    }
}

// ---------------------------------------------------------------------------
// Scores via HMMA bf16x3 + fused exp (no-max, clamp 80):
// writes UNNORMALIZED exp probs bf16 hi/lo to g_ph/g_pl (lower tiles only).
// ---------------------------------------------------------------------------
#define ROW2 144
#define STILE (128 * ROW2)     // 18432
#define SC_SMEM (4 * STILE)    // 73728

__global__ __launch_bounds__(256, 2) void scores_mma(const float* __restrict__ mask)
{
    extern __shared__ char smem[];
    const uint32_t sb = smem_u32(smem);
    const int head = blockIdx.y;
    int t = blockIdx.x, qb = 0;
    while (t >= qb + 1) { t -= qb + 1; qb++; }
    const int kb = t;
    const int b = head >> 4;

    const int tid = threadIdx.x;
    const int lane = tid & 31;
    const int wid = tid >> 5;
    const int wm = wid & 3;
    const int wn = wid >> 2;
    const int g8 = lane >> 3;
    const int r8 = lane & 7;

    const __nv_bfloat16* srcs[4] = {
        g_qh + ((size_t)head * S_ + qb * 128) * HD_,
        g_ql + ((size_t)head * S_ + qb * 128) * HD_,
        g_kh + ((size_t)head * S_ + kb * 128) * HD_,
        g_kl + ((size_t)head * S_ + kb * 128) * HD_};

    #pragma unroll
    for (int tt = 0; tt < 16; tt++) {
        int idx = tid + tt * 256;
        int tile = idx >> 10;
        int r = (idx >> 3) & 127;
        int ch = idx & 7;
        cp16(sb + (uint32_t)tile * STILE + (uint32_t)r * ROW2 + ch * 16,
             srcs[tile] + (size_t)r * HD_ + ch * 8);
    }
    asm volatile("cp.async.commit_group;");
    asm volatile("cp.async.wait_group 0;");
    __syncthreads();

    float acc[2][8][4];
    #pragma unroll
    for (int i = 0; i < 2; i++)
        #pragma unroll
        for (int j = 0; j < 8; j++)
            #pragma unroll
            for (int q = 0; q < 4; q++) acc[i][j][q] = 0.0f;

    #pragma unroll
    for (int kk = 0; kk < 4; kk++) {
        uint32_t ah[2][4], al[2][4];
        #pragma unroll
        for (int i = 0; i < 2; i++) {
            uint32_t row = wm * 32 + i * 16 + r8 + ((g8 & 1) << 3);
            uint32_t colb = kk * 32 + ((g8 >> 1) << 4);
            uint32_t a = sb + row * ROW2 + colb;
            ldm_x4(ah[i], a);
            ldm_x4(al[i], a + STILE);
        }
        #pragma unroll
        for (int jj = 0; jj < 4; jj++) {
            uint32_t nrow = wn * 64 + jj * 16 + r8 + ((g8 >> 1) << 3);
            uint32_t colb = kk * 32 + ((g8 & 1) << 4);
            uint32_t bptr = sb + 2 * STILE + nrow * ROW2 + colb;
            uint32_t bh[4], bl[4];
            ldm_x4(bh, bptr);
            ldm_x4(bl, bptr + STILE);
            #pragma unroll
            for (int i = 0; i < 2; i++) {
                mma_bf16(acc[i][2 * jj + 0], ah[i], bh[0], bh[1]);
                mma_bf16(acc[i][2 * jj + 1], ah[i], bh[2], bh[3]);
                mma_bf16(acc[i][2 * jj + 0], ah[i], bl[0], bl[1]);
                mma_bf16(acc[i][2 * jj + 1], ah[i], bl[2], bl[3]);
                mma_bf16(acc[i][2 * jj + 0], al[i], bh[0], bh[1]);
                mma_bf16(acc[i][2 * jj + 1], al[i], bh[2], bh[3]);
            }
        }
    }

    const bool diag = (qb == kb);
    const float* mrow = mask + b * S_;
    #pragma unroll
    for (int i = 0; i < 2; i++) {
        #pragma unroll
        for (int j = 0; j < 8; j++) {
            const int qi0 = qb * 128 + wm * 32 + i * 16 + (lane >> 2);
            const int kj = kb * 128 + wn * 64 + j * 8 + (lane & 3) * 2;
            float2 mv = *reinterpret_cast<const float2*>(mrow + kj);
            float s0 = fminf(acc[i][j][0] * 0.125f + mv.x, 80.0f);
            float s1 = fminf(acc[i][j][1] * 0.125f + mv.y, 80.0f);
            float s2 = fminf(acc[i][j][2] * 0.125f + mv.x, 80.0f);
            float s3 = fminf(acc[i][j][3] * 0.125f + mv.y, 80.0f);
            float e0 = __expf(s0), e1 = __expf(s1);
            float e2 = __expf(s2), e3 = __expf(s3);
            if (diag) {
                if (kj + 0 > qi0) e0 = 0.0f;
                if (kj + 1 > qi0) e1 = 0.0f;
                if (kj + 0 > qi0 + 8) e2 = 0.0f;
                if (kj + 1 > qi0 + 8) e3 = 0.0f;
            }
            size_t off = ((size_t)head * S_ + qi0) * S_ + kj;
            split_store(g_ph + off, g_pl + off, make_float2(e0, e1));
            split_store(g_ph + off + 8 * S_, g_pl + off + 8 * S_,
                        make_float2(e2, e3));
        }
    }
}

// ---------------------------------------------------------------------------
// AV via HMMA bf16x3 on UNNORMALIZED probs; rowsums via P x ones MMA.
// ---------------------------------------------------------------------------
#define AV_P  18432              // P tile bytes (128 x 144)
#define AV_V  9216               // V tile bytes (64 x 144)
#define AV_STG (2 * AV_P + 2 * AV_V)   // 55296
#define AV_SMEM (2 * AV_STG)           // 110592
#define ONES_BF16X2 0x3F803F80u

__global__ __launch_bounds__(256, 2) void av_mma()
{
    extern __shared__ char smem[];
    const uint32_t sb = smem_u32(smem);
    const int head = blockIdx.y;
    const int qb = 7 - blockIdx.x;     // big tiles first
    const int b = head >> 4;
    const int h = head & 15;

    const int tid = threadIdx.x;
    const int lane = tid & 31;
    const int wid = tid >> 5;
    const int wm = wid & 3;
    const int wn = wid >> 2;
    const int g8 = lane >> 3;
    const int r8 = lane & 7;

    const __nv_bfloat16* Phb = g_ph + ((size_t)head * S_ + qb * 128) * S_;
    const __nv_bfloat16* Plb = g_pl + ((size_t)head * S_ + qb * 128) * S_;
    const __nv_bfloat16* Vhb = g_vh + (size_t)head * S_ * HD_;
    const __nv_bfloat16* Vlb = g_vl + (size_t)head * S_ * HD_;

    const int nch = 2 * (qb + 1);      // K-chunks of 64

    auto issue = [&](int c) {
        const int k0 = c * 64;
        const uint32_t stage = sb + (uint32_t)(c & 1) * AV_STG;
        #pragma unroll
        for (int t = 0; t < 12; t++) {
            int idx = tid + t * 256;
            if (idx < 2048) {
                int tile = idx >> 10;              // 0 Ph, 1 Pl
                int r = (idx >> 3) & 127;
                int ch = idx & 7;
                const __nv_bfloat16* g = (tile ? Plb : Phb) + (size_t)r * S_ + k0 + ch * 8;
                cp16(stage + (uint32_t)tile * AV_P + (uint32_t)r * ROW2 + ch * 16, g);
            } else {
                int v = idx - 2048;
                int tile = v >> 9;                 // 0 Vh, 1 Vl
                int r = (v >> 3) & 63;
                int ch = v & 7;
                const __nv_bfloat16* g = (tile ? Vlb : Vhb) + (size_t)(k0 + r) * HD_ + ch * 8;
                cp16(stage + 2 * AV_P + (uint32_t)tile * AV_V + (uint32_t)r * ROW2 + ch * 16, g);
            }
        }
        asm volatile("cp.async.commit_group;");
    };

    float acc[2][4][4];
    #pragma unroll
    for (int i = 0; i < 2; i++)
        #pragma unroll
        for (int j = 0; j < 4; j++)
            #pragma unroll
            for (int q = 0; q < 4; q++) acc[i][j][q] = 0.0f;
    float accS[2][4];
    #pragma unroll
    for (int i = 0; i < 2; i++)
        #pragma unroll
        for (int q = 0; q < 4; q++) accS[i][q] = 0.0f;

    issue(0);
    for (int c = 0; c < nch; c++) {
        if (c + 1 < nch) {
            issue(c + 1);
            asm volatile("cp.async.wait_group 1;");
        } else {
            asm volatile("cp.async.wait_group 0;");
        }
        __syncthreads();
        const uint32_t stage = sb + (uint32_t)(c & 1) * AV_STG;

        #pragma unroll
        for (int kk = 0; kk < 4; kk++) {
            uint32_t ph[2][4], pl[2][4];
            #pragma unroll
            for (int i = 0; i < 2; i++) {
                uint32_t row = wm * 32 + i * 16 + r8 + ((g8 & 1) << 3);
                uint32_t colb = kk * 32 + ((g8 >> 1) << 4);
                uint32_t a = stage + row * ROW2 + colb;
                ldm_x4(ph[i], a);
                ldm_x4(pl[i], a + AV_P);
            }
            if (wn == 0) {       // rowsum accumulators via P x ones
                mma_bf16(accS[0], ph[0], ONES_BF16X2, ONES_BF16X2);
                mma_bf16(accS[1], ph[1], ONES_BF16X2, ONES_BF16X2);
                mma_bf16(accS[0], pl[0], ONES_BF16X2, ONES_BF16X2);
                mma_bf16(accS[1], pl[1], ONES_BF16X2, ONES_BF16X2);
            }
            #pragma unroll
            for (int jj = 0; jj < 2; jj++) {
                uint32_t row = kk * 16 + r8 + ((g8 & 1) << 3);
                uint32_t colb = (wn * 32 + jj * 16 + ((g8 >> 1) << 3)) * 2;
                uint32_t bptr = stage + 2 * AV_P + row * ROW2 + colb;
                uint32_t bh[4], bl[4];
                ldm_x4_t(bh, bptr);
                ldm_x4_t(bl, bptr + AV_V);
                #pragma unroll
                for (int i = 0; i < 2; i++) {
                    mma_bf16(acc[i][2 * jj + 0], ph[i], bh[0], bh[1]);
                    mma_bf16(acc[i][2 * jj + 1], ph[i], bh[2], bh[3]);
                    mma_bf16(acc[i][2 * jj + 0], ph[i], bl[0], bl[1]);
                    mma_bf16(acc[i][2 * jj + 1], ph[i], bl[2], bl[3]);
                    mma_bf16(acc[i][2 * jj + 0], pl[i], bh[0], bh[1]);
                    mma_bf16(acc[i][2 * jj + 1], pl[i], bh[2], bh[3]);
                }
            }
        }
        __syncthreads();
    }

    // inv exchange: wn==0 holds rowsums (all 4 lanes of a quad identical)
    float* invbuf = reinterpret_cast<float*>(smem);
    if (wn == 0 && (lane & 3) == 0) {
        #pragma unroll
        for (int i = 0; i < 2; i++) {
            const int rl = wm * 32 + i * 16 + (lane >> 2);
            float iv0 = 1.0f / accS[i][0];
            float iv1 = 1.0f / accS[i][2];
            invbuf[rl] = iv0;
            invbuf[rl + 8] = iv1;
            g_inv[(size_t)head * S_ + qb * 128 + rl] = iv0;
            g_inv[(size_t)head * S_ + qb * 128 + rl + 8] = iv1;
        }
    }
    __syncthreads();

    // epilogue -> ctx bf16 hi/lo at [b*S+s, h*64+d], scaled by inv
    #pragma unroll
    for (int i = 0; i < 2; i++) {
        const int rl = wm * 32 + i * 16 + (lane >> 2);
        const float iv0 = invbuf[rl];
        const float iv1 = invbuf[rl + 8];
        #pragma unroll
        for (int j = 0; j < 4; j++) {
            const int s0 = qb * 128 + rl;
            const int d0 = wn * 32 + j * 8 + (lane & 3) * 2;
            float2 lo = make_float2(acc[i][j][0] * iv0, acc[i][j][1] * iv0);
            float2 hi = make_float2(acc[i][j][2] * iv1, acc[i][j][3] * iv1);
            size_t off0 = (size_t)(b * S_ + s0) * D_ + h * HD_ + d0;
            split_store(g_ch + off0, g_cl + off0, lo);
            size_t off1 = (size_t)(b * S_ + s0 + 8) * D_ + h * HD_ + d0;
            split_store(g_ch + off1, g_cl + off1, hi);
        }
    }
}

// ---------------------------------------------------------------------------
// Normalize: w[head,qi,j] = (ph+pl)*inv for j<valid, 0 beyond. DRAM-bound;
// runs on a second stream concurrently with the proj GEMM.
// ---------------------------------------------------------------------------
__global__ __launch_bounds__(256) void normalize_w(float* __restrict__ w_out)
{
    const int idx = blockIdx.x;          // head*S + qi
    const int qi = idx & (S_ - 1);
    const int valid = ((qi >> 7) + 1) << 7;
    const float inv = g_inv[idx];
    const int j0 = threadIdx.x * 4;

    float4 o;
    if (j0 < valid) {
        size_t off = (size_t)idx * S_ + j0;
        __nv_bfloat162 h0 = *reinterpret_cast<const __nv_bfloat162*>(g_ph + off);
        __nv_bfloat162 h1 = *reinterpret_cast<const __nv_bfloat162*>(g_ph + off + 2);
        __nv_bfloat162 l0 = *reinterpret_cast<const __nv_bfloat162*>(g_pl + off);
        __nv_bfloat162 l1 = *reinterpret_cast<const __nv_bfloat162*>(g_pl + off + 2);
        o.x = (__bfloat162float(h0.x) + __bfloat162float(l0.x)) * inv;
        o.y = (__bfloat162float(h0.y) + __bfloat162float(l0.y)) * inv;
        o.z = (__bfloat162float(h1.x) + __bfloat162float(l1.x)) * inv;
        o.w = (__bfloat162float(h1.y) + __bfloat162float(l1.y)) * inv;
    } else {
        o = make_float4(0.f, 0.f, 0.f, 0.f);
    }
    *reinterpret_cast<float4*>(w_out + (size_t)idx * S_ + j0) = o;
}

// ---------------------------------------------------------------------------
extern "C" void kernel_launch(void* const* d_in, const int* in_sizes, int n_in,
                              void* d_out, int out_size)
{
    const float* x      = (const float*)d_in[0];
    const float* mask   = (const float*)d_in[1];
    const float* w_attn = (const float*)d_in[2];
    const float* b_attn = (const float*)d_in[3];
    const float* w_proj = (const float*)d_in[4];
    const float* b_proj = (const float*)d_in[5];

    float* out   = (float*)d_out;
    float* a_out = out;                         // [B,S,D]
    float* w_out = out + (size_t)M_ * D_;       // [B,H,S,S]

    __nv_bfloat16 *xh, *xl, *wah, *wal, *wph, *wpl, *ch, *cl;
    cudaGetSymbolAddress((void**)&xh,  g_xh);
    cudaGetSymbolAddress((void**)&xl,  g_xl);
    cudaGetSymbolAddress((void**)&wah, g_wah);
    cudaGetSymbolAddress((void**)&wal, g_wal);
    cudaGetSymbolAddress((void**)&wph, g_wph);
    cudaGetSymbolAddress((void**)&wpl, g_wpl);
    cudaGetSymbolAddress((void**)&ch,  g_ch);
    cudaGetSymbolAddress((void**)&cl,  g_cl);

    static cudaStream_t s2 = nullptr;
    static cudaEvent_t ev0 = nullptr, evA = nullptr, evV = nullptr,
                       evWp = nullptr, evF = nullptr, evN = nullptr;
    if (!s2) {
        cudaStreamCreateWithFlags(&s2, cudaStreamNonBlocking);
        cudaEventCreateWithFlags(&ev0, cudaEventDisableTiming);
        cudaEventCreateWithFlags(&evA, cudaEventDisableTiming);
        cudaEventCreateWithFlags(&evV, cudaEventDisableTiming);
        cudaEventCreateWithFlags(&evWp, cudaEventDisableTiming);
        cudaEventCreateWithFlags(&evF, cudaEventDisableTiming);
        cudaEventCreateWithFlags(&evN, cudaEventDisableTiming);
    }

    cudaFuncSetAttribute(gemm_mma_bf16x3,
                         cudaFuncAttributeMaxDynamicSharedMemorySize, GEMM_SMEM);
    cudaFuncSetAttribute(scores_mma,
                         cudaFuncAttributeMaxDynamicSharedMemorySize, SC_SMEM);
    cudaFuncSetAttribute(av_mma,
                         cudaFuncAttributeMaxDynamicSharedMemorySize, AV_SMEM);

    // Join s2 into the capture FIRST (event from origin stream), then branch.
    cudaEventRecord(ev0, 0);
    cudaStreamWaitEvent(s2, ev0, 0);

    // converts: x + w_attn on main; w_proj on s2 (now capture-legal)
    convert_transpose<<<dim3(D_ / 32, D_ / 32), 256, 0, s2>>>(w_proj, wph, wpl, D_, D_);
    cudaEventRecord(evWp, s2);
    convert_rm<<<(M_ * D_ / 4 + 255) / 256, 256>>>(x, xh, xl, (size_t)M_ * D_);
    convert_transpose<<<dim3(TD_ / 32, D_ / 32), 256>>>(w_attn, wah, wal, D_, TD_);
    cudaEventRecord(evA, 0);

    // V-part GEMM (cols 2048..3071) on s2, concurrent with QK + scores on main
    cudaStreamWaitEvent(s2, evA, 0);
    gemm_mma_bf16x3<<<dim3(8, M_ / 128), 128, GEMM_SMEM, s2>>>(
        xh, xl, wah, wal, b_attn, nullptr, D_, TD_, 0, 2048);
    cudaEventRecord(evV, s2);

    // QK-part GEMM (cols 0..2047) then scores on main
    gemm_mma_bf16x3<<<dim3(16, M_ / 128), 128, GEMM_SMEM>>>(
        xh, xl, wah, wal, b_attn, nullptr, D_, TD_, 0, 0);
    scores_mma<<<dim3(36, NH_), 256, SC_SMEM>>>(mask);

    // av needs scores (in-order) + V (event)
    cudaStreamWaitEvent(0, evV, 0);
    av_mma<<<dim3(8, NH_), 256, AV_SMEM>>>();

    // Fork: normalize w on s2  ||  proj GEMM on main
    cudaEventRecord(evF, 0);
    cudaStreamWaitEvent(s2, evF, 0);
    normalize_w<<<NH_ * S_, 256, 0, s2>>>(w_out);
    cudaEventRecord(evN, s2);

    cudaStreamWaitEvent(0, evWp, 0);
    gemm_mma_bf16x3<<<dim3(D_ / 128, M_ / 128), 128, GEMM_SMEM>>>(
        ch, cl, wph, wpl, b_proj, a_out, D_, D_, 1, 0);

    cudaStreamWaitEvent(0, evN, 0);
}